// round 7
// baseline (speedup 1.0000x reference)
#include <cuda_runtime.h>
#include <cuda_bf16.h>
#include <math.h>
#include <stdint.h>

#define Bd 4
#define Td 2048
#define Cd 1024
#define Hd 16
#define DHd 64
#define Mtot (Bd * Td)      // 8192
#define K3 (3 * Cd)         // 3072 split-K: A=[hi|hi|lo], B=[hi|lo|hi]

typedef uint32_t u32;

// ---- scratch (__device__ globals; allocation-free rule) --------------------
__device__ float g_qkv[(size_t)Mtot * 3 * Cd];
__device__ __nv_bfloat16 g_x3[(size_t)Mtot * K3];
__device__ __nv_bfloat16 g_y3[(size_t)Mtot * K3];
__device__ __nv_bfloat16 g_wa3[(size_t)(3 * Cd) * K3];
__device__ __nv_bfloat16 g_wp3[(size_t)Cd * K3];
__device__ __nv_bfloat16 g_qhi[(size_t)Bd * Hd * Td * DHd];
__device__ __nv_bfloat16 g_qlo[(size_t)Bd * Hd * Td * DHd];
__device__ __nv_bfloat16 g_khi[(size_t)Bd * Hd * Td * DHd];
__device__ __nv_bfloat16 g_klo[(size_t)Bd * Hd * Td * DHd];
__device__ __nv_bfloat16 g_vthi[(size_t)Bd * Hd * DHd * Td];
__device__ __nv_bfloat16 g_vtlo[(size_t)Bd * Hd * DHd * Td];

// ---- helpers ----------------------------------------------------------------
__device__ __forceinline__ u32 smem_u32(const void* p) {
    u32 a;
    asm("{ .reg .u64 t; cvta.to.shared.u64 t, %1; cvt.u32.u64 %0, t; }" : "=r"(a) : "l"(p));
    return a;
}
__device__ __forceinline__ void ldm4(u32& r0, u32& r1, u32& r2, u32& r3, u32 addr) {
    asm volatile("ldmatrix.sync.aligned.m8n8.x4.shared.b16 {%0,%1,%2,%3}, [%4];"
                 : "=r"(r0), "=r"(r1), "=r"(r2), "=r"(r3) : "r"(addr));
}
__device__ __forceinline__ void mma16816(float* d, const u32* a, u32 b0, u32 b1) {
    asm volatile(
        "mma.sync.aligned.m16n8k16.row.col.f32.bf16.bf16.f32 "
        "{%0,%1,%2,%3}, {%4,%5,%6,%7}, {%8,%9}, {%0,%1,%2,%3};"
        : "+f"(d[0]), "+f"(d[1]), "+f"(d[2]), "+f"(d[3])
        : "r"(a[0]), "r"(a[1]), "r"(a[2]), "r"(a[3]), "r"(b0), "r"(b1));
}
__device__ __forceinline__ void cpa16(u32 dst, const void* src) {
    asm volatile("cp.async.cg.shared.global [%0], [%1], 16;" :: "r"(dst), "l"(src) : "memory");
}
__device__ __forceinline__ void cpa_commit() {
    asm volatile("cp.async.commit_group;" ::: "memory");
}
__device__ __forceinline__ u32 cvt_bf16x2(float hi, float lo) {
    u32 r;
    asm("cvt.rn.bf16x2.f32 %0, %1, %2;" : "=r"(r) : "f"(hi), "f"(lo));
    return r;
}
__device__ __forceinline__ float bf_lo(u32 r) { return __uint_as_float(r << 16); }
__device__ __forceinline__ float bf_hi(u32 r) { return __uint_as_float(r & 0xFFFF0000u); }

// FFMA-only exp (rel err ~1e-7), valid for x <= 0
__device__ __forceinline__ float fexp(float x) {
    x = fmaxf(x, -80.f);
    float t  = fmaf(x, 1.4426950408889634f, 12582912.0f);
    float fi = t - 12582912.0f;
    float f  = fmaf(x, 1.4426950408889634f, -fi);
    float p  = 0.00015403530393381609f;
    p = fmaf(p, f, 0.0013333558146428443f);
    p = fmaf(p, f, 0.009618129107628477f);
    p = fmaf(p, f, 0.05550410866482158f);
    p = fmaf(p, f, 0.2402265069591007f);
    p = fmaf(p, f, 0.6931471805599453f);
    p = fmaf(p, f, 1.0f);
    int ei = __float_as_int(t) - 0x4B400000;
    return __uint_as_float(__float_as_int(p) + (ei << 23));
}

// ---------------------------------------------------------------------------
// fp32 -> bf16x3 split conversions
// ---------------------------------------------------------------------------
__global__ void split_rows3(const float* __restrict__ in, __nv_bfloat16* __restrict__ out,
                            int R, int Cc)
{
    int idx = blockIdx.x * blockDim.x + threadIdx.x;
    int total = R * Cc / 4;
    if (idx >= total) return;
    int c = (idx % (Cc / 4)) * 4;
    int r = idx / (Cc / 4);
    float4 v = *(const float4*)(in + (size_t)r * Cc + c);
    __nv_bfloat162 h0 = __floats2bfloat162_rn(v.x, v.y);
    __nv_bfloat162 h1 = __floats2bfloat162_rn(v.z, v.w);
    __nv_bfloat162 l0 = __floats2bfloat162_rn(v.x - __bfloat162float(h0.x),
                                              v.y - __bfloat162float(h0.y));
    __nv_bfloat162 l1 = __floats2bfloat162_rn(v.z - __bfloat162float(h1.x),
                                              v.w - __bfloat162float(h1.y));
    __nv_bfloat16* o = out + (size_t)r * (3 * Cc) + c;
    uint2 hv = make_uint2(*(u32*)&h0, *(u32*)&h1);
    uint2 lv = make_uint2(*(u32*)&l0, *(u32*)&l1);
    *(uint2*)(o)          = hv;
    *(uint2*)(o + Cc)     = hv;
    *(uint2*)(o + 2 * Cc) = lv;
}

__global__ void __launch_bounds__(256) split_tr3(
    const float* __restrict__ w, __nv_bfloat16* __restrict__ out, int K, int N)
{
    __shared__ float tile[32][33];
    const int tid = threadIdx.x;
    const int n0 = blockIdx.x * 32, k0 = blockIdx.y * 32;
    {
        const int r = tid >> 3, c = (tid & 7) * 4;
        float4 v = *(const float4*)(w + (size_t)(k0 + r) * N + n0 + c);
        tile[r][c] = v.x; tile[r][c + 1] = v.y; tile[r][c + 2] = v.z; tile[r][c + 3] = v.w;
    }
    __syncthreads();
    {
        const int n = tid >> 3, c = (tid & 7) * 4;
        u32 hw[2], lw[2];
#pragma unroll
        for (int p = 0; p < 2; p++) {
            float v0 = tile[c + 2 * p][n], v1 = tile[c + 2 * p + 1][n];
            hw[p] = cvt_bf16x2(v1, v0);
            lw[p] = cvt_bf16x2(v1 - bf_hi(hw[p]), v0 - bf_lo(hw[p]));
        }
        __nv_bfloat16* o = out + (size_t)(n0 + n) * (3 * K) + k0 + c;
        *(uint2*)(o)         = make_uint2(hw[0], hw[1]);
        *(uint2*)(o + K)     = make_uint2(lw[0], lw[1]);
        *(uint2*)(o + 2 * K) = make_uint2(hw[0], hw[1]);
    }
}

// ---------------------------------------------------------------------------
// GEMM (HMMA): 3-stage cp.async ring, ONE __syncthreads per k-chunk.
// CTA 128x128, 4 warps (2m x 2n), warp 64x64. KC=64 per chunk, 48 chunks.
// ---------------------------------------------------------------------------
#define GROWB 144
#define GBUFB (128 * GROWB)          // 18432 B per operand per stage
#define GSTAGES 3
__global__ void __launch_bounds__(128) gemm_mma(
    const __nv_bfloat16* __restrict__ A, const __nv_bfloat16* __restrict__ Bt,
    float* __restrict__ C, int Nout)
{
    extern __shared__ __align__(16) char sm[];
    const u32 sA = smem_u32(sm);                       // [3][128][144B]
    const u32 sB = sA + GSTAGES * GBUFB;               // [3][128][144B]

    const int tid = threadIdx.x, wid = tid >> 5, lane = tid & 31;
    const int wm = wid >> 1, wn = wid & 1;
    const int g = lane >> 2, t = lane & 3;
    const int row0 = blockIdx.y * 128, col0 = blockIdx.x * 128;

    const int lr = tid >> 3;
    const __nv_bfloat16* Ag = A + (size_t)(row0 + lr) * K3 + (tid & 7) * 8;
    const __nv_bfloat16* Bg = Bt + (size_t)(col0 + lr) * K3 + (tid & 7) * 8;
    const u32 da0 = sA + lr * GROWB + (tid & 7) * 16;
    const u32 db0 = sB + lr * GROWB + (tid & 7) * 16;

    float acc[4][8][4];
#pragma unroll
    for (int i = 0; i < 4; i++)
#pragma unroll
        for (int j = 0; j < 8; j++)
#pragma unroll
            for (int r = 0; r < 4; r++) acc[i][j][r] = 0.f;

    const int a_row_off = (64 * wm + (lane & 15)) * GROWB + ((lane >> 4) << 4);
    const int b_row_off = (64 * wn + (lane & 7) + 8 * ((lane >> 4) & 1)) * GROWB
                        + 16 * ((lane >> 3) & 1);

    // prefetch stages 0,1
#pragma unroll
    for (int s = 0; s < 2; s++) {
        const size_t ko = (size_t)s * 64;
#pragma unroll
        for (int i = 0; i < 8; i++) {
            cpa16(da0 + s * GBUFB + i * 16 * GROWB, Ag + (size_t)(16 * i) * K3 + ko);
            cpa16(db0 + s * GBUFB + i * 16 * GROWB, Bg + (size_t)(16 * i) * K3 + ko);
        }
        cpa_commit();
    }

    int stage = 0;
    for (int kc = 0; kc < 48; kc++) {
        asm volatile("cp.async.wait_group 1;" ::: "memory");
        __syncthreads();

        // issue stage kc+2 (its buffer was consumed at kc-1; barrier above protects)
        if (kc + 2 < 48) {
            const int ns = (stage + 2 >= GSTAGES) ? stage + 2 - GSTAGES : stage + 2;
            const size_t ko = (size_t)(kc + 2) * 64;
#pragma unroll
            for (int i = 0; i < 8; i++) {
                cpa16(da0 + ns * GBUFB + i * 16 * GROWB, Ag + (size_t)(16 * i) * K3 + ko);
                cpa16(db0 + ns * GBUFB + i * 16 * GROWB, Bg + (size_t)(16 * i) * K3 + ko);
            }
            cpa_commit();
        }

        const u32 abase = sA + stage * GBUFB + a_row_off;
        const u32 bbase = sB + stage * GBUFB + b_row_off;
#pragma unroll
        for (int kt = 0; kt < 4; kt++) {
            u32 af[4][4], bf[4][4];
#pragma unroll
            for (int mt = 0; mt < 4; mt++)
                ldm4(af[mt][0], af[mt][1], af[mt][2], af[mt][3],
                     abase + mt * (16 * GROWB) + kt * 32);
#pragma unroll
            for (int np = 0; np < 4; np++)
                ldm4(bf[np][0], bf[np][1], bf[np][2], bf[np][3],
                     bbase + np * (16 * GROWB) + kt * 32);
#pragma unroll
            for (int mt = 0; mt < 4; mt++)
#pragma unroll
                for (int np = 0; np < 4; np++) {
                    mma16816(acc[mt][2 * np],     af[mt], bf[np][0], bf[np][1]);
                    mma16816(acc[mt][2 * np + 1], af[mt], bf[np][2], bf[np][3]);
                }
        }
        stage = (stage + 1 >= GSTAGES) ? 0 : stage + 1;
    }

#pragma unroll
    for (int mt = 0; mt < 4; mt++) {
        const int r0 = row0 + 64 * wm + 16 * mt + g;
#pragma unroll
        for (int nt = 0; nt < 8; nt++) {
            const int col = col0 + 64 * wn + 8 * nt + 2 * t;
            *(float2*)(C + (size_t)r0 * Nout + col)       = make_float2(acc[mt][nt][0], acc[mt][nt][1]);
            *(float2*)(C + (size_t)(r0 + 8) * Nout + col) = make_float2(acc[mt][nt][2], acc[mt][nt][3]);
        }
    }
}

// ---------------------------------------------------------------------------
// prep_attn — unchanged
// ---------------------------------------------------------------------------
__global__ void __launch_bounds__(256) prep_attn(const float* __restrict__ qkv)
{
    __shared__ __nv_bfloat16 tvhi[64][72];
    __shared__ __nv_bfloat16 tvlo[64][72];
    const int tid = threadIdx.x;
    const int tb = blockIdx.x, bh = blockIdx.y;
    const int b = bh >> 4, h = bh & 15;

#pragma unroll
    for (int i = 0; i < 4; i++) {
        const int u = tid + 256 * i;
        const int tr = u >> 4;
        const int d4 = (u & 15) * 4;
        const int tg = tb * 64 + tr;
        const size_t base = ((size_t)(b * Td + tg)) * 3072 + h * 64 + d4;
        float4 q = *(const float4*)(qkv + base);
        float4 k = *(const float4*)(qkv + base + 1024);
        float4 v = *(const float4*)(qkv + base + 2048);
        q.x *= 0.125f; q.y *= 0.125f; q.z *= 0.125f; q.w *= 0.125f;

        const size_t qidx = ((size_t)bh * Td + tg) * 64 + d4;
        __nv_bfloat162 qh0 = __floats2bfloat162_rn(q.x, q.y);
        __nv_bfloat162 qh1 = __floats2bfloat162_rn(q.z, q.w);
        __nv_bfloat162 ql0 = __floats2bfloat162_rn(q.x - __bfloat162float(qh0.x), q.y - __bfloat162float(qh0.y));
        __nv_bfloat162 ql1 = __floats2bfloat162_rn(q.z - __bfloat162float(qh1.x), q.w - __bfloat162float(qh1.y));
        *(uint2*)(g_qhi + qidx) = make_uint2(*(u32*)&qh0, *(u32*)&qh1);
        *(uint2*)(g_qlo + qidx) = make_uint2(*(u32*)&ql0, *(u32*)&ql1);

        __nv_bfloat162 kh0 = __floats2bfloat162_rn(k.x, k.y);
        __nv_bfloat162 kh1 = __floats2bfloat162_rn(k.z, k.w);
        __nv_bfloat162 kl0 = __floats2bfloat162_rn(k.x - __bfloat162float(kh0.x), k.y - __bfloat162float(kh0.y));
        __nv_bfloat162 kl1 = __floats2bfloat162_rn(k.z - __bfloat162float(kh1.x), k.w - __bfloat162float(kh1.y));
        *(uint2*)(g_khi + qidx) = make_uint2(*(u32*)&kh0, *(u32*)&kh1);
        *(uint2*)(g_klo + qidx) = make_uint2(*(u32*)&kl0, *(u32*)&kl1);

        float vv[4] = {v.x, v.y, v.z, v.w};
#pragma unroll
        for (int j = 0; j < 4; j++) {
            __nv_bfloat16 hi = __float2bfloat16(vv[j]);
            __nv_bfloat16 lo = __float2bfloat16(vv[j] - __bfloat162float(hi));
            tvhi[d4 + j][tr] = hi;
            tvlo[d4 + j][tr] = lo;
        }
    }
    __syncthreads();
#pragma unroll
    for (int i = 0; i < 2; i++) {
        const int u = tid + 256 * i;
        const int d = u >> 3;
        const int tc = (u & 7) * 8;
        const size_t vidx = ((size_t)bh * 64 + d) * Td + tb * 64 + tc;
        *(uint4*)(g_vthi + vidx) = *(uint4*)&tvhi[d][tc];
        *(uint4*)(g_vtlo + vidx) = *(uint4*)&tvlo[d][tc];
    }
}

// ---------------------------------------------------------------------------
// flash_mma: R5 version (q-tile 64, 4 warps x 16 q-rows) — known good.
// ---------------------------------------------------------------------------
__global__ void __launch_bounds__(128) flash_mma(__nv_bfloat16* __restrict__ y3)
{
    __shared__ __align__(16) __nv_bfloat16 s_t[4][64 * 72];
    const int tid = threadIdx.x, wid = tid >> 5, lane = tid & 31;
    const int g = lane >> 2, t = lane & 3;
    const int qb = gridDim.x - 1 - blockIdx.x;
    const int bh = blockIdx.y;
    const int b = bh >> 4, h = bh & 15;

    const size_t qkbase = (size_t)bh * Td * 64;
    const size_t vtbase = (size_t)bh * 64 * Td;

    const u32 s0 = smem_u32(s_t);
    const u32 sKhi = s0, sKlo = s0 + 9216, sVhi = s0 + 18432, sVlo = s0 + 27648;

    const int a_off = (16 * wid + (lane & 15)) * 144 + ((lane >> 4) << 4);
    const int b_off = ((lane & 7) + 8 * ((lane >> 4) & 1)) * 144 + 16 * ((lane >> 3) & 1);

#pragma unroll
    for (int i = 0; i < 4; i++) {
        const int u = tid + 128 * i;
        const int r = u >> 3, c = (u & 7) * 8;
        const size_t gq = qkbase + (size_t)(qb * 64 + r) * 64 + c;
        *(uint4*)&s_t[0][r * 72 + c] = *(const uint4*)(g_qhi + gq);
        *(uint4*)&s_t[1][r * 72 + c] = *(const uint4*)(g_qlo + gq);
    }
    __syncthreads();
    u32 qh[4][4], ql[4][4];
#pragma unroll
    for (int kt = 0; kt < 4; kt++) {
        ldm4(qh[kt][0], qh[kt][1], qh[kt][2], qh[kt][3], sKhi + a_off + kt * 32);
        ldm4(ql[kt][0], ql[kt][1], ql[kt][2], ql[kt][3], sKlo + a_off + kt * 32);
    }

    float o[8][4];
#pragma unroll
    for (int j = 0; j < 8; j++)
#pragma unroll
        for (int r = 0; r < 4; r++) o[j][r] = 0.f;
    float m0 = -1e30f, m1 = -1e30f, l0 = 0.f, l1 = 0.f;

    for (int kb = 0; kb <= qb; kb++) {
        __syncthreads();
#pragma unroll
        for (int i = 0; i < 4; i++) {
            const int u = tid + 128 * i;
            const int r = u >> 3, c = (u & 7) * 8;
            const size_t gk = qkbase + (size_t)(kb * 64 + r) * 64 + c;
            const size_t gv = vtbase + (size_t)r * Td + kb * 64 + c;
            *(uint4*)&s_t[0][r * 72 + c] = *(const uint4*)(g_khi + gk);
            *(uint4*)&s_t[1][r * 72 + c] = *(const uint4*)(g_klo + gk);
            *(uint4*)&s_t[2][r * 72 + c] = *(const uint4*)(g_vthi + gv);
            *(uint4*)&s_t[3][r * 72 + c] = *(const uint4*)(g_vtlo + gv);
        }
        __syncthreads();

        float s[8][4];
#pragma unroll
        for (int j = 0; j < 8; j++)
#pragma unroll
            for (int r = 0; r < 4; r++) s[j][r] = 0.f;
#pragma unroll
        for (int np = 0; np < 4; np++) {
#pragma unroll
            for (int kt = 0; kt < 4; kt++) {
                const int off = b_off + np * (16 * 144) + kt * 32;
                u32 h0, h1, h2, h3, e0, e1, e2, e3;
                ldm4(h0, h1, h2, h3, sKhi + off);
                mma16816(s[2 * np],     qh[kt], h0, h1);
                mma16816(s[2 * np + 1], qh[kt], h2, h3);
                mma16816(s[2 * np],     ql[kt], h0, h1);
                mma16816(s[2 * np + 1], ql[kt], h2, h3);
                ldm4(e0, e1, e2, e3, sKlo + off);
                mma16816(s[2 * np],     qh[kt], e0, e1);
                mma16816(s[2 * np + 1], qh[kt], e2, e3);
            }
        }

        if (kb == qb) {
            const int qg0 = qb * 64 + 16 * wid + g;
            const int qg1 = qg0 + 8;
#pragma unroll
            for (int nt = 0; nt < 8; nt++) {
                const int kg = kb * 64 + 8 * nt + 2 * t;
                if (kg > qg0)     s[nt][0] = -1e30f;
                if (kg + 1 > qg0) s[nt][1] = -1e30f;
                if (kg > qg1)     s[nt][2] = -1e30f;
                if (kg + 1 > qg1) s[nt][3] = -1e30f;
            }
        }

        float ml0 = -1e30f, ml1 = -1e30f;
#pragma unroll
        for (int nt = 0; nt < 8; nt++) {
            ml0 = fmaxf(ml0, fmaxf(s[nt][0], s[nt][1]));
            ml1 = fmaxf(ml1, fmaxf(s[nt][2], s[nt][3]));
        }
        ml0 = fmaxf(ml0, __shfl_xor_sync(0xffffffffu, ml0, 1));
        ml0 = fmaxf(ml0, __shfl_xor_sync(0xffffffffu, ml0, 2));
        ml1 = fmaxf(ml1, __shfl_xor_sync(0xffffffffu, ml1, 1));
        ml1 = fmaxf(ml1, __shfl_xor_sync(0xffffffffu, ml1, 2));
        const float mn0 = fmaxf(m0, ml0), mn1 = fmaxf(m1, ml1);
        const float cr0 = fexp(m0 - mn0), cr1 = fexp(m1 - mn1);
        m0 = mn0; m1 = mn1;
        float ls0 = 0.f, ls1 = 0.f;
#pragma unroll
        for (int nt = 0; nt < 8; nt++) {
            s[nt][0] = fexp(s[nt][0] - mn0); ls0 += s[nt][0];
            s[nt][1] = fexp(s[nt][1] - mn0); ls0 += s[nt][1];
            s[nt][2] = fexp(s[nt][2] - mn1); ls1 += s[nt][2];
            s[nt][3] = fexp(s[nt][3] - mn1); ls1 += s[nt][3];
        }
        ls0 += __shfl_xor_sync(0xffffffffu, ls0, 1);
        ls0 += __shfl_xor_sync(0xffffffffu, ls0, 2);
        ls1 += __shfl_xor_sync(0xffffffffu, ls1, 1);
        ls1 += __shfl_xor_sync(0xffffffffu, ls1, 2);
        l0 = l0 * cr0 + ls0;
        l1 = l1 * cr1 + ls1;
#pragma unroll
        for (int j = 0; j < 8; j++) {
            o[j][0] *= cr0; o[j][1] *= cr0; o[j][2] *= cr1; o[j][3] *= cr1;
        }

#pragma unroll
        for (int kt = 0; kt < 4; kt++) {
            u32 ph[4], pl[4];
            ph[0] = cvt_bf16x2(s[2 * kt][1],     s[2 * kt][0]);
            ph[1] = cvt_bf16x2(s[2 * kt][3],     s[2 * kt][2]);
            ph[2] = cvt_bf16x2(s[2 * kt + 1][1], s[2 * kt + 1][0]);
            ph[3] = cvt_bf16x2(s[2 * kt + 1][3], s[2 * kt + 1][2]);
            pl[0] = cvt_bf16x2(s[2 * kt][1] - bf_hi(ph[0]),     s[2 * kt][0] - bf_lo(ph[0]));
            pl[1] = cvt_bf16x2(s[2 * kt][3] - bf_hi(ph[1]),     s[2 * kt][2] - bf_lo(ph[1]));
            pl[2] = cvt_bf16x2(s[2 * kt + 1][1] - bf_hi(ph[2]), s[2 * kt + 1][0] - bf_lo(ph[2]));
            pl[3] = cvt_bf16x2(s[2 * kt + 1][3] - bf_hi(ph[3]), s[2 * kt + 1][2] - bf_lo(ph[3]));
#pragma unroll
            for (int np = 0; np < 4; np++) {
                const int off = b_off + np * (16 * 144) + kt * 32;
                u32 v0, v1, v2, v3, w0, w1, w2, w3;
                ldm4(v0, v1, v2, v3, sVhi + off);
                mma16816(o[2 * np],     ph, v0, v1);
                mma16816(o[2 * np + 1], ph, v2, v3);
                mma16816(o[2 * np],     pl, v0, v1);
                mma16816(o[2 * np + 1], pl, v2, v3);
                ldm4(w0, w1, w2, w3, sVlo + off);
                mma16816(o[2 * np],     ph, w0, w1);
                mma16816(o[2 * np + 1], ph, w2, w3);
            }
        }
    }

    const float inv0 = 1.f / l0, inv1 = 1.f / l1;
    const int tg0 = qb * 64 + 16 * wid + g;
    const size_t m0i = (size_t)(b * Td + tg0) * K3;
    const size_t m1i = (size_t)(b * Td + tg0 + 8) * K3;
#pragma unroll
    for (int nt = 0; nt < 8; nt++) {
        const int col = h * 64 + 8 * nt + 2 * t;
        {
            const float f0 = o[nt][0] * inv0, f1 = o[nt][1] * inv0;
            const u32 hi = cvt_bf16x2(f1, f0);
            const u32 lo = cvt_bf16x2(f1 - bf_hi(hi), f0 - bf_lo(hi));
            *(u32*)(y3 + m0i + col)        = hi;
            *(u32*)(y3 + m0i + col + 1024) = hi;
            *(u32*)(y3 + m0i + col + 2048) = lo;
        }
        {
            const float f2 = o[nt][2] * inv1, f3 = o[nt][3] * inv1;
            const u32 hi = cvt_bf16x2(f3, f2);
            const u32 lo = cvt_bf16x2(f3 - bf_hi(hi), f2 - bf_lo(hi));
            *(u32*)(y3 + m1i + col)        = hi;
            *(u32*)(y3 + m1i + col + 1024) = hi;
            *(u32*)(y3 + m1i + col + 2048) = lo;
        }
    }
}

// ---------------------------------------------------------------------------
extern "C" void kernel_launch(void* const* d_in, const int* in_sizes, int n_in,
                              void* d_out, int out_size)
{
    const float* x      = (const float*)d_in[0];
    const float* w_attn = (const float*)d_in[1];
    const float* w_proj = (const float*)d_in[2];
    float* out = (float*)d_out;

    float* qkv;
    __nv_bfloat16 *x3, *y3, *wa3, *wp3;
    cudaGetSymbolAddress((void**)&qkv, g_qkv);
    cudaGetSymbolAddress((void**)&x3, g_x3);
    cudaGetSymbolAddress((void**)&y3, g_y3);
    cudaGetSymbolAddress((void**)&wa3, g_wa3);
    cudaGetSymbolAddress((void**)&wp3, g_wp3);

    const int gemm_smem = 2 * GSTAGES * GBUFB;   // 110592 B
    cudaFuncSetAttribute(gemm_mma, cudaFuncAttributeMaxDynamicSharedMemorySize, gemm_smem);

    split_rows3<<<(Mtot * Cd / 4 + 255) / 256, 256>>>(x, x3, Mtot, Cd);
    split_tr3<<<dim3(3 * Cd / 32, Cd / 32), 256>>>(w_attn, wa3, Cd, 3 * Cd);
    split_tr3<<<dim3(Cd / 32, Cd / 32), 256>>>(w_proj, wp3, Cd, Cd);

    dim3 g1(3 * Cd / 128, Mtot / 128);    // (24, 64)
    gemm_mma<<<g1, 128, gemm_smem>>>(x3, wa3, qkv, 3 * Cd);

    dim3 gp(Td / 64, Bd * Hd);
    prep_attn<<<gp, 256>>>(qkv);

    dim3 g2(Td / 64, Bd * Hd);            // (32, 64)
    flash_mma<<<g2, 128>>>(y3);

    dim3 g3(Cd / 128, Mtot / 128);        // (8, 64)
    gemm_mma<<<g3, 128, gemm_smem>>>(y3, wp3, out, Cd);
}

// round 8
// speedup vs baseline: 1.0434x; 1.0434x over previous
#include <cuda_runtime.h>
#include <cuda_bf16.h>
#include <math.h>
#include <stdint.h>

#define Bd 4
#define Td 2048
#define Cd 1024
#define Hd 16
#define DHd 64
#define Mtot (Bd * Td)      // 8192
#define K3 (3 * Cd)         // 3072 split-K: A=[hi|hi|lo], B=[hi|lo|hi]

typedef uint32_t u32;

// ---- scratch (__device__ globals; allocation-free rule) --------------------
__device__ float g_qkv[(size_t)Mtot * 3 * Cd];
__device__ __nv_bfloat16 g_x3[(size_t)Mtot * K3];
__device__ __nv_bfloat16 g_y3[(size_t)Mtot * K3];
__device__ __nv_bfloat16 g_wa3[(size_t)(3 * Cd) * K3];
__device__ __nv_bfloat16 g_wp3[(size_t)Cd * K3];
__device__ __nv_bfloat16 g_qhi[(size_t)Bd * Hd * Td * DHd];
__device__ __nv_bfloat16 g_qlo[(size_t)Bd * Hd * Td * DHd];
__device__ __nv_bfloat16 g_khi[(size_t)Bd * Hd * Td * DHd];
__device__ __nv_bfloat16 g_klo[(size_t)Bd * Hd * Td * DHd];
__device__ __nv_bfloat16 g_vthi[(size_t)Bd * Hd * DHd * Td];
__device__ __nv_bfloat16 g_vtlo[(size_t)Bd * Hd * DHd * Td];

// ---- helpers ----------------------------------------------------------------
__device__ __forceinline__ u32 smem_u32(const void* p) {
    u32 a;
    asm("{ .reg .u64 t; cvta.to.shared.u64 t, %1; cvt.u32.u64 %0, t; }" : "=r"(a) : "l"(p));
    return a;
}
__device__ __forceinline__ void ldm4(u32& r0, u32& r1, u32& r2, u32& r3, u32 addr) {
    asm volatile("ldmatrix.sync.aligned.m8n8.x4.shared.b16 {%0,%1,%2,%3}, [%4];"
                 : "=r"(r0), "=r"(r1), "=r"(r2), "=r"(r3) : "r"(addr));
}
__device__ __forceinline__ void mma16816(float* d, const u32* a, u32 b0, u32 b1) {
    asm volatile(
        "mma.sync.aligned.m16n8k16.row.col.f32.bf16.bf16.f32 "
        "{%0,%1,%2,%3}, {%4,%5,%6,%7}, {%8,%9}, {%0,%1,%2,%3};"
        : "+f"(d[0]), "+f"(d[1]), "+f"(d[2]), "+f"(d[3])
        : "r"(a[0]), "r"(a[1]), "r"(a[2]), "r"(a[3]), "r"(b0), "r"(b1));
}
__device__ __forceinline__ void cpa16(u32 dst, const void* src) {
    asm volatile("cp.async.cg.shared.global [%0], [%1], 16;" :: "r"(dst), "l"(src) : "memory");
}
__device__ __forceinline__ void cpa_commit() {
    asm volatile("cp.async.commit_group;" ::: "memory");
}
__device__ __forceinline__ u32 cvt_bf16x2(float hi, float lo) {
    u32 r;
    asm("cvt.rn.bf16x2.f32 %0, %1, %2;" : "=r"(r) : "f"(hi), "f"(lo));
    return r;
}
__device__ __forceinline__ float bf_lo(u32 r) { return __uint_as_float(r << 16); }
__device__ __forceinline__ float bf_hi(u32 r) { return __uint_as_float(r & 0xFFFF0000u); }

// FFMA-only exp (rel err ~1e-7), valid for x <= 0
__device__ __forceinline__ float fexp(float x) {
    x = fmaxf(x, -80.f);
    float t  = fmaf(x, 1.4426950408889634f, 12582912.0f);
    float fi = t - 12582912.0f;
    float f  = fmaf(x, 1.4426950408889634f, -fi);
    float p  = 0.00015403530393381609f;
    p = fmaf(p, f, 0.0013333558146428443f);
    p = fmaf(p, f, 0.009618129107628477f);
    p = fmaf(p, f, 0.05550410866482158f);
    p = fmaf(p, f, 0.2402265069591007f);
    p = fmaf(p, f, 0.6931471805599453f);
    p = fmaf(p, f, 1.0f);
    int ei = __float_as_int(t) - 0x4B400000;
    return __uint_as_float(__float_as_int(p) + (ei << 23));
}

// ---------------------------------------------------------------------------
// fp32 -> bf16x3 split conversions
// ---------------------------------------------------------------------------
__global__ void split_rows3(const float* __restrict__ in, __nv_bfloat16* __restrict__ out,
                            int R, int Cc)
{
    int idx = blockIdx.x * blockDim.x + threadIdx.x;
    int total = R * Cc / 4;
    if (idx >= total) return;
    int c = (idx % (Cc / 4)) * 4;
    int r = idx / (Cc / 4);
    float4 v = *(const float4*)(in + (size_t)r * Cc + c);
    __nv_bfloat162 h0 = __floats2bfloat162_rn(v.x, v.y);
    __nv_bfloat162 h1 = __floats2bfloat162_rn(v.z, v.w);
    __nv_bfloat162 l0 = __floats2bfloat162_rn(v.x - __bfloat162float(h0.x),
                                              v.y - __bfloat162float(h0.y));
    __nv_bfloat162 l1 = __floats2bfloat162_rn(v.z - __bfloat162float(h1.x),
                                              v.w - __bfloat162float(h1.y));
    __nv_bfloat16* o = out + (size_t)r * (3 * Cc) + c;
    uint2 hv = make_uint2(*(u32*)&h0, *(u32*)&h1);
    uint2 lv = make_uint2(*(u32*)&l0, *(u32*)&l1);
    *(uint2*)(o)          = hv;
    *(uint2*)(o + Cc)     = hv;
    *(uint2*)(o + 2 * Cc) = lv;
}

__global__ void __launch_bounds__(256) split_tr3(
    const float* __restrict__ w, __nv_bfloat16* __restrict__ out, int K, int N)
{
    __shared__ float tile[32][33];
    const int tid = threadIdx.x;
    const int n0 = blockIdx.x * 32, k0 = blockIdx.y * 32;
    {
        const int r = tid >> 3, c = (tid & 7) * 4;
        float4 v = *(const float4*)(w + (size_t)(k0 + r) * N + n0 + c);
        tile[r][c] = v.x; tile[r][c + 1] = v.y; tile[r][c + 2] = v.z; tile[r][c + 3] = v.w;
    }
    __syncthreads();
    {
        const int n = tid >> 3, c = (tid & 7) * 4;
        u32 hw[2], lw[2];
#pragma unroll
        for (int p = 0; p < 2; p++) {
            float v0 = tile[c + 2 * p][n], v1 = tile[c + 2 * p + 1][n];
            hw[p] = cvt_bf16x2(v1, v0);
            lw[p] = cvt_bf16x2(v1 - bf_hi(hw[p]), v0 - bf_lo(hw[p]));
        }
        __nv_bfloat16* o = out + (size_t)(n0 + n) * (3 * K) + k0 + c;
        *(uint2*)(o)         = make_uint2(hw[0], hw[1]);
        *(uint2*)(o + K)     = make_uint2(lw[0], lw[1]);
        *(uint2*)(o + 2 * K) = make_uint2(hw[0], hw[1]);
    }
}

// ---------------------------------------------------------------------------
// GEMM (HMMA) — R5 version (known best: 409 us QKV), double-buffered cp.async.
// ---------------------------------------------------------------------------
#define GROWB 144
#define GBUFB (128 * GROWB)
__global__ void __launch_bounds__(128) gemm_mma(
    const __nv_bfloat16* __restrict__ A, const __nv_bfloat16* __restrict__ Bt,
    float* __restrict__ C, int Nout)
{
    extern __shared__ __align__(16) char sm[];
    const u32 sA = smem_u32(sm);
    const u32 sB = sA + 2 * GBUFB;

    const int tid = threadIdx.x, wid = tid >> 5, lane = tid & 31;
    const int wm = wid >> 1, wn = wid & 1;
    const int g = lane >> 2, t = lane & 3;
    const int row0 = blockIdx.y * 128, col0 = blockIdx.x * 128;

    const int lr = tid >> 3;
    const __nv_bfloat16* Ag = A + (size_t)(row0 + lr) * K3 + (tid & 7) * 8;
    const __nv_bfloat16* Bg = Bt + (size_t)(col0 + lr) * K3 + (tid & 7) * 8;
    const u32 da0 = sA + lr * GROWB + (tid & 7) * 16;
    const u32 db0 = sB + lr * GROWB + (tid & 7) * 16;

    float acc[4][8][4];
#pragma unroll
    for (int i = 0; i < 4; i++)
#pragma unroll
        for (int j = 0; j < 8; j++)
#pragma unroll
            for (int r = 0; r < 4; r++) acc[i][j][r] = 0.f;

    const int a_row_off = (64 * wm + (lane & 15)) * GROWB + ((lane >> 4) << 4);
    const int b_row_off = (64 * wn + (lane & 7) + 8 * ((lane >> 4) & 1)) * GROWB
                        + 16 * ((lane >> 3) & 1);

#pragma unroll
    for (int i = 0; i < 8; i++) {
        cpa16(da0 + i * 16 * GROWB, Ag + (size_t)(16 * i) * K3);
        cpa16(db0 + i * 16 * GROWB, Bg + (size_t)(16 * i) * K3);
    }
    cpa_commit();

    for (int kc = 0; kc < 48; kc++) {
        const int buf = kc & 1;
        if (kc < 47) {
            const int nb = buf ^ 1;
            const size_t ko = (size_t)(kc + 1) * 64;
#pragma unroll
            for (int i = 0; i < 8; i++) {
                cpa16(da0 + nb * GBUFB + i * 16 * GROWB, Ag + (size_t)(16 * i) * K3 + ko);
                cpa16(db0 + nb * GBUFB + i * 16 * GROWB, Bg + (size_t)(16 * i) * K3 + ko);
            }
            cpa_commit();
            asm volatile("cp.async.wait_group 1;" ::: "memory");
        } else {
            asm volatile("cp.async.wait_group 0;" ::: "memory");
        }
        __syncthreads();

        const u32 abase = sA + buf * GBUFB + a_row_off;
        const u32 bbase = sB + buf * GBUFB + b_row_off;
#pragma unroll
        for (int kt = 0; kt < 4; kt++) {
            u32 af[4][4], bf[4][4];
#pragma unroll
            for (int mt = 0; mt < 4; mt++)
                ldm4(af[mt][0], af[mt][1], af[mt][2], af[mt][3],
                     abase + mt * (16 * GROWB) + kt * 32);
#pragma unroll
            for (int np = 0; np < 4; np++)
                ldm4(bf[np][0], bf[np][1], bf[np][2], bf[np][3],
                     bbase + np * (16 * GROWB) + kt * 32);
#pragma unroll
            for (int mt = 0; mt < 4; mt++)
#pragma unroll
                for (int np = 0; np < 4; np++) {
                    mma16816(acc[mt][2 * np],     af[mt], bf[np][0], bf[np][1]);
                    mma16816(acc[mt][2 * np + 1], af[mt], bf[np][2], bf[np][3]);
                }
        }
        __syncthreads();
    }

#pragma unroll
    for (int mt = 0; mt < 4; mt++) {
        const int r0 = row0 + 64 * wm + 16 * mt + g;
#pragma unroll
        for (int nt = 0; nt < 8; nt++) {
            const int col = col0 + 64 * wn + 8 * nt + 2 * t;
            *(float2*)(C + (size_t)r0 * Nout + col)       = make_float2(acc[mt][nt][0], acc[mt][nt][1]);
            *(float2*)(C + (size_t)(r0 + 8) * Nout + col) = make_float2(acc[mt][nt][2], acc[mt][nt][3]);
        }
    }
}

// ---------------------------------------------------------------------------
// prep_attn — unchanged
// ---------------------------------------------------------------------------
__global__ void __launch_bounds__(256) prep_attn(const float* __restrict__ qkv)
{
    __shared__ __nv_bfloat16 tvhi[64][72];
    __shared__ __nv_bfloat16 tvlo[64][72];
    const int tid = threadIdx.x;
    const int tb = blockIdx.x, bh = blockIdx.y;
    const int b = bh >> 4, h = bh & 15;

#pragma unroll
    for (int i = 0; i < 4; i++) {
        const int u = tid + 256 * i;
        const int tr = u >> 4;
        const int d4 = (u & 15) * 4;
        const int tg = tb * 64 + tr;
        const size_t base = ((size_t)(b * Td + tg)) * 3072 + h * 64 + d4;
        float4 q = *(const float4*)(qkv + base);
        float4 k = *(const float4*)(qkv + base + 1024);
        float4 v = *(const float4*)(qkv + base + 2048);
        q.x *= 0.125f; q.y *= 0.125f; q.z *= 0.125f; q.w *= 0.125f;

        const size_t qidx = ((size_t)bh * Td + tg) * 64 + d4;
        __nv_bfloat162 qh0 = __floats2bfloat162_rn(q.x, q.y);
        __nv_bfloat162 qh1 = __floats2bfloat162_rn(q.z, q.w);
        __nv_bfloat162 ql0 = __floats2bfloat162_rn(q.x - __bfloat162float(qh0.x), q.y - __bfloat162float(qh0.y));
        __nv_bfloat162 ql1 = __floats2bfloat162_rn(q.z - __bfloat162float(qh1.x), q.w - __bfloat162float(qh1.y));
        *(uint2*)(g_qhi + qidx) = make_uint2(*(u32*)&qh0, *(u32*)&qh1);
        *(uint2*)(g_qlo + qidx) = make_uint2(*(u32*)&ql0, *(u32*)&ql1);

        __nv_bfloat162 kh0 = __floats2bfloat162_rn(k.x, k.y);
        __nv_bfloat162 kh1 = __floats2bfloat162_rn(k.z, k.w);
        __nv_bfloat162 kl0 = __floats2bfloat162_rn(k.x - __bfloat162float(kh0.x), k.y - __bfloat162float(kh0.y));
        __nv_bfloat162 kl1 = __floats2bfloat162_rn(k.z - __bfloat162float(kh1.x), k.w - __bfloat162float(kh1.y));
        *(uint2*)(g_khi + qidx) = make_uint2(*(u32*)&kh0, *(u32*)&kh1);
        *(uint2*)(g_klo + qidx) = make_uint2(*(u32*)&kl0, *(u32*)&kl1);

        float vv[4] = {v.x, v.y, v.z, v.w};
#pragma unroll
        for (int j = 0; j < 4; j++) {
            __nv_bfloat16 hi = __float2bfloat16(vv[j]);
            __nv_bfloat16 lo = __float2bfloat16(vv[j] - __bfloat162float(hi));
            tvhi[d4 + j][tr] = hi;
            tvlo[d4 + j][tr] = lo;
        }
    }
    __syncthreads();
#pragma unroll
    for (int i = 0; i < 2; i++) {
        const int u = tid + 256 * i;
        const int d = u >> 3;
        const int tc = (u & 7) * 8;
        const size_t vidx = ((size_t)bh * 64 + d) * Td + tb * 64 + tc;
        *(uint4*)(g_vthi + vidx) = *(uint4*)&tvhi[d][tc];
        *(uint4*)(g_vtlo + vidx) = *(uint4*)&tvlo[d][tc];
    }
}

// ---------------------------------------------------------------------------
// flash_mma: q-tile 64, 4 warps x 16 q-rows (R5 structure) + 2-stage cp.async
// ring for K/V tiles. smem 2 x 36864 = 73728 B (matches reg-limited residency).
// ---------------------------------------------------------------------------
#define FTILEB 9216                     // 64*72*2 bytes per array
#define FSTGB (4 * FTILEB)              // Khi,Klo,Vhi,Vlo per stage = 36864
__global__ void __launch_bounds__(128) flash_mma(__nv_bfloat16* __restrict__ y3)
{
    extern __shared__ __align__(16) char fsm[];
    const u32 s0 = smem_u32(fsm);       // [2][4][9216]

    const int tid = threadIdx.x, wid = tid >> 5, lane = tid & 31;
    const int g = lane >> 2, t = lane & 3;
    const int qb = gridDim.x - 1 - blockIdx.x;
    const int bh = blockIdx.y;
    const int b = bh >> 4, h = bh & 15;

    const size_t qkbase = (size_t)bh * Td * 64;
    const size_t vtbase = (size_t)bh * 64 * Td;

    const int a_off = (16 * wid + (lane & 15)) * 144 + ((lane >> 4) << 4);
    const int b_off = ((lane & 7) + 8 * ((lane >> 4) & 1)) * 144 + 16 * ((lane >> 3) & 1);

    // per-thread load mapping (shared by Q staging and K/V prefetch)
    const int plr[4] = {(tid + 0) >> 3, (tid + 128) >> 3, (tid + 256) >> 3, (tid + 384) >> 3};
    const int plc = (tid & 7) * 8;      // element col

    // ---- stage Q tile into stage-0 (arrays 0,1), ldmatrix to regs ----
#pragma unroll
    for (int i = 0; i < 4; i++) {
        const int r = plr[i];
        const size_t gq = qkbase + (size_t)(qb * 64 + r) * 64 + plc;
        *(uint4*)(fsm + 0 * FTILEB + r * 144 + plc * 2) = *(const uint4*)(g_qhi + gq);
        *(uint4*)(fsm + 1 * FTILEB + r * 144 + plc * 2) = *(const uint4*)(g_qlo + gq);
    }
    __syncthreads();
    u32 qh[4][4], ql[4][4];
#pragma unroll
    for (int kt = 0; kt < 4; kt++) {
        ldm4(qh[kt][0], qh[kt][1], qh[kt][2], qh[kt][3], s0 + 0 * FTILEB + a_off + kt * 32);
        ldm4(ql[kt][0], ql[kt][1], ql[kt][2], ql[kt][3], s0 + 1 * FTILEB + a_off + kt * 32);
    }
    __syncthreads();   // Q reads done; stage 0 free for prefetch

    // ---- prefetch k-tiles 0 (stage 0) and 1 (stage 1) ----
#pragma unroll
    for (int st = 0; st < 2; st++) {
        if (st <= qb) {
            const u32 sb = s0 + st * FSTGB;
#pragma unroll
            for (int i = 0; i < 4; i++) {
                const int r = plr[i];
                const size_t gk = qkbase + (size_t)(st * 64 + r) * 64 + plc;
                const size_t gv = vtbase + (size_t)r * Td + st * 64 + plc;
                const u32 d = r * 144 + plc * 2;
                cpa16(sb + 0 * FTILEB + d, g_khi + gk);
                cpa16(sb + 1 * FTILEB + d, g_klo + gk);
                cpa16(sb + 2 * FTILEB + d, g_vthi + gv);
                cpa16(sb + 3 * FTILEB + d, g_vtlo + gv);
            }
        }
        cpa_commit();   // commit even if empty to keep group accounting uniform
    }

    float o[8][4];
#pragma unroll
    for (int j = 0; j < 8; j++)
#pragma unroll
        for (int r = 0; r < 4; r++) o[j][r] = 0.f;
    float m0 = -1e30f, m1 = -1e30f, l0 = 0.f, l1 = 0.f;

    for (int kb = 0; kb <= qb; kb++) {
        const u32 sb = s0 + (kb & 1) * FSTGB;
        if (kb < qb) {
            asm volatile("cp.async.wait_group 1;" ::: "memory");
        } else {
            asm volatile("cp.async.wait_group 0;" ::: "memory");
        }
        __syncthreads();
        const u32 sKhi = sb, sKlo = sb + FTILEB, sVhi = sb + 2 * FTILEB, sVlo = sb + 3 * FTILEB;

        float s[8][4];
#pragma unroll
        for (int j = 0; j < 8; j++)
#pragma unroll
            for (int r = 0; r < 4; r++) s[j][r] = 0.f;
#pragma unroll
        for (int np = 0; np < 4; np++) {
#pragma unroll
            for (int kt = 0; kt < 4; kt++) {
                const int off = b_off + np * (16 * 144) + kt * 32;
                u32 h0, h1, h2, h3, e0, e1, e2, e3;
                ldm4(h0, h1, h2, h3, sKhi + off);
                mma16816(s[2 * np],     qh[kt], h0, h1);
                mma16816(s[2 * np + 1], qh[kt], h2, h3);
                mma16816(s[2 * np],     ql[kt], h0, h1);
                mma16816(s[2 * np + 1], ql[kt], h2, h3);
                ldm4(e0, e1, e2, e3, sKlo + off);
                mma16816(s[2 * np],     qh[kt], e0, e1);
                mma16816(s[2 * np + 1], qh[kt], e2, e3);
            }
        }

        if (kb == qb) {
            const int qg0 = qb * 64 + 16 * wid + g;
            const int qg1 = qg0 + 8;
#pragma unroll
            for (int nt = 0; nt < 8; nt++) {
                const int kg = kb * 64 + 8 * nt + 2 * t;
                if (kg > qg0)     s[nt][0] = -1e30f;
                if (kg + 1 > qg0) s[nt][1] = -1e30f;
                if (kg > qg1)     s[nt][2] = -1e30f;
                if (kg + 1 > qg1) s[nt][3] = -1e30f;
            }
        }

        float ml0 = -1e30f, ml1 = -1e30f;
#pragma unroll
        for (int nt = 0; nt < 8; nt++) {
            ml0 = fmaxf(ml0, fmaxf(s[nt][0], s[nt][1]));
            ml1 = fmaxf(ml1, fmaxf(s[nt][2], s[nt][3]));
        }
        ml0 = fmaxf(ml0, __shfl_xor_sync(0xffffffffu, ml0, 1));
        ml0 = fmaxf(ml0, __shfl_xor_sync(0xffffffffu, ml0, 2));
        ml1 = fmaxf(ml1, __shfl_xor_sync(0xffffffffu, ml1, 1));
        ml1 = fmaxf(ml1, __shfl_xor_sync(0xffffffffu, ml1, 2));
        const float mn0 = fmaxf(m0, ml0), mn1 = fmaxf(m1, ml1);
        const float cr0 = fexp(m0 - mn0), cr1 = fexp(m1 - mn1);
        m0 = mn0; m1 = mn1;
        float ls0 = 0.f, ls1 = 0.f;
#pragma unroll
        for (int nt = 0; nt < 8; nt++) {
            s[nt][0] = fexp(s[nt][0] - mn0); ls0 += s[nt][0];
            s[nt][1] = fexp(s[nt][1] - mn0); ls0 += s[nt][1];
            s[nt][2] = fexp(s[nt][2] - mn1); ls1 += s[nt][2];
            s[nt][3] = fexp(s[nt][3] - mn1); ls1 += s[nt][3];
        }
        ls0 += __shfl_xor_sync(0xffffffffu, ls0, 1);
        ls0 += __shfl_xor_sync(0xffffffffu, ls0, 2);
        ls1 += __shfl_xor_sync(0xffffffffu, ls1, 1);
        ls1 += __shfl_xor_sync(0xffffffffu, ls1, 2);
        l0 = l0 * cr0 + ls0;
        l1 = l1 * cr1 + ls1;
#pragma unroll
        for (int j = 0; j < 8; j++) {
            o[j][0] *= cr0; o[j][1] *= cr0; o[j][2] *= cr1; o[j][3] *= cr1;
        }

#pragma unroll
        for (int kt = 0; kt < 4; kt++) {
            u32 ph[4], pl[4];
            ph[0] = cvt_bf16x2(s[2 * kt][1],     s[2 * kt][0]);
            ph[1] = cvt_bf16x2(s[2 * kt][3],     s[2 * kt][2]);
            ph[2] = cvt_bf16x2(s[2 * kt + 1][1], s[2 * kt + 1][0]);
            ph[3] = cvt_bf16x2(s[2 * kt + 1][3], s[2 * kt + 1][2]);
            pl[0] = cvt_bf16x2(s[2 * kt][1] - bf_hi(ph[0]),     s[2 * kt][0] - bf_lo(ph[0]));
            pl[1] = cvt_bf16x2(s[2 * kt][3] - bf_hi(ph[1]),     s[2 * kt][2] - bf_lo(ph[1]));
            pl[2] = cvt_bf16x2(s[2 * kt + 1][1] - bf_hi(ph[2]), s[2 * kt + 1][0] - bf_lo(ph[2]));
            pl[3] = cvt_bf16x2(s[2 * kt + 1][3] - bf_hi(ph[3]), s[2 * kt + 1][2] - bf_lo(ph[3]));
#pragma unroll
            for (int np = 0; np < 4; np++) {
                const int off = b_off + np * (16 * 144) + kt * 32;
                u32 v0, v1, v2, v3, w0, w1, w2, w3;
                ldm4(v0, v1, v2, v3, sVhi + off);
                mma16816(o[2 * np],     ph, v0, v1);
                mma16816(o[2 * np + 1], ph, v2, v3);
                mma16816(o[2 * np],     pl, v0, v1);
                mma16816(o[2 * np + 1], pl, v2, v3);
                ldm4(w0, w1, w2, w3, sVlo + off);
                mma16816(o[2 * np],     ph, w0, w1);
                mma16816(o[2 * np + 1], ph, w2, w3);
            }
        }

        // stage (kb&1) fully consumed; prefetch k-tile kb+2 into it
        __syncthreads();
        if (kb + 2 <= qb) {
            const u32 nsb = sb;   // same stage index (2-stage ring)
            const int nk = kb + 2;
#pragma unroll
            for (int i = 0; i < 4; i++) {
                const int r = plr[i];
                const size_t gk = qkbase + (size_t)(nk * 64 + r) * 64 + plc;
                const size_t gv = vtbase + (size_t)r * Td + nk * 64 + plc;
                const u32 d = r * 144 + plc * 2;
                cpa16(nsb + 0 * FTILEB + d, g_khi + gk);
                cpa16(nsb + 1 * FTILEB + d, g_klo + gk);
                cpa16(nsb + 2 * FTILEB + d, g_vthi + gv);
                cpa16(nsb + 3 * FTILEB + d, g_vtlo + gv);
            }
        }
        cpa_commit();
    }

    const float inv0 = 1.f / l0, inv1 = 1.f / l1;
    const int tg0 = qb * 64 + 16 * wid + g;
    const size_t m0i = (size_t)(b * Td + tg0) * K3;
    const size_t m1i = (size_t)(b * Td + tg0 + 8) * K3;
#pragma unroll
    for (int nt = 0; nt < 8; nt++) {
        const int col = h * 64 + 8 * nt + 2 * t;
        {
            const float f0 = o[nt][0] * inv0, f1 = o[nt][1] * inv0;
            const u32 hi = cvt_bf16x2(f1, f0);
            const u32 lo = cvt_bf16x2(f1 - bf_hi(hi), f0 - bf_lo(hi));
            *(u32*)(y3 + m0i + col)        = hi;
            *(u32*)(y3 + m0i + col + 1024) = hi;
            *(u32*)(y3 + m0i + col + 2048) = lo;
        }
        {
            const float f2 = o[nt][2] * inv1, f3 = o[nt][3] * inv1;
            const u32 hi = cvt_bf16x2(f3, f2);
            const u32 lo = cvt_bf16x2(f3 - bf_hi(hi), f2 - bf_lo(hi));
            *(u32*)(y3 + m1i + col)        = hi;
            *(u32*)(y3 + m1i + col + 1024) = hi;
            *(u32*)(y3 + m1i + col + 2048) = lo;
        }
    }
}

// ---------------------------------------------------------------------------
extern "C" void kernel_launch(void* const* d_in, const int* in_sizes, int n_in,
                              void* d_out, int out_size)
{
    const float* x      = (const float*)d_in[0];
    const float* w_attn = (const float*)d_in[1];
    const float* w_proj = (const float*)d_in[2];
    float* out = (float*)d_out;

    float* qkv;
    __nv_bfloat16 *x3, *y3, *wa3, *wp3;
    cudaGetSymbolAddress((void**)&qkv, g_qkv);
    cudaGetSymbolAddress((void**)&x3, g_x3);
    cudaGetSymbolAddress((void**)&y3, g_y3);
    cudaGetSymbolAddress((void**)&wa3, g_wa3);
    cudaGetSymbolAddress((void**)&wp3, g_wp3);

    const int gemm_smem = 4 * GBUFB;        // 73728 B
    cudaFuncSetAttribute(gemm_mma, cudaFuncAttributeMaxDynamicSharedMemorySize, gemm_smem);
    const int flash_smem = 2 * FSTGB;       // 73728 B
    cudaFuncSetAttribute(flash_mma, cudaFuncAttributeMaxDynamicSharedMemorySize, flash_smem);

    split_rows3<<<(Mtot * Cd / 4 + 255) / 256, 256>>>(x, x3, Mtot, Cd);
    split_tr3<<<dim3(3 * Cd / 32, Cd / 32), 256>>>(w_attn, wa3, Cd, 3 * Cd);
    split_tr3<<<dim3(Cd / 32, Cd / 32), 256>>>(w_proj, wp3, Cd, Cd);

    dim3 g1(3 * Cd / 128, Mtot / 128);    // (24, 64)
    gemm_mma<<<g1, 128, gemm_smem>>>(x3, wa3, qkv, 3 * Cd);

    dim3 gp(Td / 64, Bd * Hd);
    prep_attn<<<gp, 256>>>(qkv);

    dim3 g2(Td / 64, Bd * Hd);            // (32, 64)
    flash_mma<<<g2, 128, flash_smem>>>(y3);

    dim3 g3(Cd / 128, Mtot / 128);        // (8, 64)
    gemm_mma<<<g3, 128, gemm_smem>>>(y3, wp3, out, Cd);
}

// round 9
// speedup vs baseline: 1.0938x; 1.0482x over previous
#include <cuda_runtime.h>
#include <cuda_bf16.h>
#include <math.h>
#include <stdint.h>

#define Bd 4
#define Td 2048
#define Cd 1024
#define Hd 16
#define DHd 64
#define Mtot (Bd * Td)      // 8192
#define K3 (3 * Cd)         // 3072 split-K: A=[hi|hi|lo], B=[hi|lo|hi]

typedef uint32_t u32;

// ---- scratch (__device__ globals; allocation-free rule) --------------------
__device__ __nv_bfloat16 g_x3[(size_t)Mtot * K3];
__device__ __nv_bfloat16 g_y3[(size_t)Mtot * K3];
__device__ __nv_bfloat16 g_wa3[(size_t)(3 * Cd) * K3];
__device__ __nv_bfloat16 g_wp3[(size_t)Cd * K3];
// attention operands, per (b,h), all [bh][t][64] row-major
__device__ __nv_bfloat16 g_qhi[(size_t)Bd * Hd * Td * DHd];
__device__ __nv_bfloat16 g_qlo[(size_t)Bd * Hd * Td * DHd];
__device__ __nv_bfloat16 g_khi[(size_t)Bd * Hd * Td * DHd];
__device__ __nv_bfloat16 g_klo[(size_t)Bd * Hd * Td * DHd];
__device__ __nv_bfloat16 g_vhi[(size_t)Bd * Hd * Td * DHd];
__device__ __nv_bfloat16 g_vlo[(size_t)Bd * Hd * Td * DHd];

// ---- helpers ----------------------------------------------------------------
__device__ __forceinline__ u32 smem_u32(const void* p) {
    u32 a;
    asm("{ .reg .u64 t; cvta.to.shared.u64 t, %1; cvt.u32.u64 %0, t; }" : "=r"(a) : "l"(p));
    return a;
}
__device__ __forceinline__ void ldm4(u32& r0, u32& r1, u32& r2, u32& r3, u32 addr) {
    asm volatile("ldmatrix.sync.aligned.m8n8.x4.shared.b16 {%0,%1,%2,%3}, [%4];"
                 : "=r"(r0), "=r"(r1), "=r"(r2), "=r"(r3) : "r"(addr));
}
__device__ __forceinline__ void ldm4t(u32& r0, u32& r1, u32& r2, u32& r3, u32 addr) {
    asm volatile("ldmatrix.sync.aligned.m8n8.x4.trans.shared.b16 {%0,%1,%2,%3}, [%4];"
                 : "=r"(r0), "=r"(r1), "=r"(r2), "=r"(r3) : "r"(addr));
}
__device__ __forceinline__ void mma16816(float* d, const u32* a, u32 b0, u32 b1) {
    asm volatile(
        "mma.sync.aligned.m16n8k16.row.col.f32.bf16.bf16.f32 "
        "{%0,%1,%2,%3}, {%4,%5,%6,%7}, {%8,%9}, {%0,%1,%2,%3};"
        : "+f"(d[0]), "+f"(d[1]), "+f"(d[2]), "+f"(d[3])
        : "r"(a[0]), "r"(a[1]), "r"(a[2]), "r"(a[3]), "r"(b0), "r"(b1));
}
__device__ __forceinline__ void cpa16(u32 dst, const void* src) {
    asm volatile("cp.async.cg.shared.global [%0], [%1], 16;" :: "r"(dst), "l"(src) : "memory");
}
__device__ __forceinline__ void cpa_commit() {
    asm volatile("cp.async.commit_group;" ::: "memory");
}
__device__ __forceinline__ u32 cvt_bf16x2(float hi, float lo) {
    u32 r;
    asm("cvt.rn.bf16x2.f32 %0, %1, %2;" : "=r"(r) : "f"(hi), "f"(lo));
    return r;
}
__device__ __forceinline__ float bf_lo(u32 r) { return __uint_as_float(r << 16); }
__device__ __forceinline__ float bf_hi(u32 r) { return __uint_as_float(r & 0xFFFF0000u); }

// FFMA-only exp (rel err ~1e-7), valid for x <= 0
__device__ __forceinline__ float fexp(float x) {
    x = fmaxf(x, -80.f);
    float t  = fmaf(x, 1.4426950408889634f, 12582912.0f);
    float fi = t - 12582912.0f;
    float f  = fmaf(x, 1.4426950408889634f, -fi);
    float p  = 0.00015403530393381609f;
    p = fmaf(p, f, 0.0013333558146428443f);
    p = fmaf(p, f, 0.009618129107628477f);
    p = fmaf(p, f, 0.05550410866482158f);
    p = fmaf(p, f, 0.2402265069591007f);
    p = fmaf(p, f, 0.6931471805599453f);
    p = fmaf(p, f, 1.0f);
    int ei = __float_as_int(t) - 0x4B400000;
    return __uint_as_float(__float_as_int(p) + (ei << 23));
}

// ---------------------------------------------------------------------------
// fp32 -> bf16x3 split conversions
// ---------------------------------------------------------------------------
__global__ void split_rows3(const float* __restrict__ in, __nv_bfloat16* __restrict__ out,
                            int R, int Cc)
{
    int idx = blockIdx.x * blockDim.x + threadIdx.x;
    int total = R * Cc / 4;
    if (idx >= total) return;
    int c = (idx % (Cc / 4)) * 4;
    int r = idx / (Cc / 4);
    float4 v = *(const float4*)(in + (size_t)r * Cc + c);
    __nv_bfloat162 h0 = __floats2bfloat162_rn(v.x, v.y);
    __nv_bfloat162 h1 = __floats2bfloat162_rn(v.z, v.w);
    __nv_bfloat162 l0 = __floats2bfloat162_rn(v.x - __bfloat162float(h0.x),
                                              v.y - __bfloat162float(h0.y));
    __nv_bfloat162 l1 = __floats2bfloat162_rn(v.z - __bfloat162float(h1.x),
                                              v.w - __bfloat162float(h1.y));
    __nv_bfloat16* o = out + (size_t)r * (3 * Cc) + c;
    uint2 hv = make_uint2(*(u32*)&h0, *(u32*)&h1);
    uint2 lv = make_uint2(*(u32*)&l0, *(u32*)&l1);
    *(uint2*)(o)          = hv;
    *(uint2*)(o + Cc)     = hv;
    *(uint2*)(o + 2 * Cc) = lv;
}

__global__ void __launch_bounds__(256) split_tr3(
    const float* __restrict__ w, __nv_bfloat16* __restrict__ out, int K, int N)
{
    __shared__ float tile[32][33];
    const int tid = threadIdx.x;
    const int n0 = blockIdx.x * 32, k0 = blockIdx.y * 32;
    {
        const int r = tid >> 3, c = (tid & 7) * 4;
        float4 v = *(const float4*)(w + (size_t)(k0 + r) * N + n0 + c);
        tile[r][c] = v.x; tile[r][c + 1] = v.y; tile[r][c + 2] = v.z; tile[r][c + 3] = v.w;
    }
    __syncthreads();
    {
        const int n = tid >> 3, c = (tid & 7) * 4;
        u32 hw[2], lw[2];
#pragma unroll
        for (int p = 0; p < 2; p++) {
            float v0 = tile[c + 2 * p][n], v1 = tile[c + 2 * p + 1][n];
            hw[p] = cvt_bf16x2(v1, v0);
            lw[p] = cvt_bf16x2(v1 - bf_hi(hw[p]), v0 - bf_lo(hw[p]));
        }
        __nv_bfloat16* o = out + (size_t)(n0 + n) * (3 * K) + k0 + c;
        *(uint2*)(o)         = make_uint2(hw[0], hw[1]);
        *(uint2*)(o + K)     = make_uint2(lw[0], lw[1]);
        *(uint2*)(o + 2 * K) = make_uint2(hw[0], hw[1]);
    }
}

// ---------------------------------------------------------------------------
// GEMM core (R5 mainloop). Two variants differ only in epilogue.
// CTA 128x128, 4 warps (2m x 2n), warp 64x64. 2-stage cp.async.
// ---------------------------------------------------------------------------
#define GROWB 144
#define GBUFB (128 * GROWB)

#define GEMM_MAINLOOP(ACC)                                                          \
    const int lr = tid >> 3;                                                        \
    const __nv_bfloat16* Ag = A + (size_t)(row0 + lr) * K3 + (tid & 7) * 8;         \
    const __nv_bfloat16* Bg = Bt + (size_t)(col0 + lr) * K3 + (tid & 7) * 8;        \
    const u32 da0 = sA + lr * GROWB + (tid & 7) * 16;                               \
    const u32 db0 = sB + lr * GROWB + (tid & 7) * 16;                               \
    const int a_row_off = (64 * wm + (lane & 15)) * GROWB + ((lane >> 4) << 4);     \
    const int b_row_off = (64 * wn + (lane & 7) + 8 * ((lane >> 4) & 1)) * GROWB    \
                        + 16 * ((lane >> 3) & 1);                                   \
    _Pragma("unroll")                                                               \
    for (int i = 0; i < 8; i++) {                                                   \
        cpa16(da0 + i * 16 * GROWB, Ag + (size_t)(16 * i) * K3);                    \
        cpa16(db0 + i * 16 * GROWB, Bg + (size_t)(16 * i) * K3);                    \
    }                                                                               \
    cpa_commit();                                                                   \
    for (int kc = 0; kc < 48; kc++) {                                               \
        const int buf = kc & 1;                                                     \
        if (kc < 47) {                                                              \
            const int nb = buf ^ 1;                                                 \
            const size_t ko = (size_t)(kc + 1) * 64;                                \
            _Pragma("unroll")                                                       \
            for (int i = 0; i < 8; i++) {                                           \
                cpa16(da0 + nb * GBUFB + i * 16 * GROWB, Ag + (size_t)(16 * i) * K3 + ko); \
                cpa16(db0 + nb * GBUFB + i * 16 * GROWB, Bg + (size_t)(16 * i) * K3 + ko); \
            }                                                                       \
            cpa_commit();                                                           \
            asm volatile("cp.async.wait_group 1;" ::: "memory");                    \
        } else {                                                                    \
            asm volatile("cp.async.wait_group 0;" ::: "memory");                    \
        }                                                                           \
        __syncthreads();                                                            \
        const u32 abase = sA + buf * GBUFB + a_row_off;                             \
        const u32 bbase = sB + buf * GBUFB + b_row_off;                             \
        _Pragma("unroll")                                                           \
        for (int kt = 0; kt < 4; kt++) {                                            \
            u32 af[4][4], bf[4][4];                                                 \
            _Pragma("unroll")                                                       \
            for (int mt = 0; mt < 4; mt++)                                          \
                ldm4(af[mt][0], af[mt][1], af[mt][2], af[mt][3],                    \
                     abase + mt * (16 * GROWB) + kt * 32);                          \
            _Pragma("unroll")                                                       \
            for (int np = 0; np < 4; np++)                                          \
                ldm4(bf[np][0], bf[np][1], bf[np][2], bf[np][3],                    \
                     bbase + np * (16 * GROWB) + kt * 32);                          \
            _Pragma("unroll")                                                       \
            for (int mt = 0; mt < 4; mt++)                                          \
                _Pragma("unroll")                                                   \
                for (int np = 0; np < 4; np++) {                                    \
                    mma16816(ACC[mt][2 * np],     af[mt], bf[np][0], bf[np][1]);    \
                    mma16816(ACC[mt][2 * np + 1], af[mt], bf[np][2], bf[np][3]);    \
                }                                                                   \
        }                                                                           \
        __syncthreads();                                                            \
    }

// Proj GEMM: fp32 output
__global__ void __launch_bounds__(128) gemm_mma(
    const __nv_bfloat16* __restrict__ A, const __nv_bfloat16* __restrict__ Bt,
    float* __restrict__ C, int Nout)
{
    extern __shared__ __align__(16) char sm[];
    const u32 sA = smem_u32(sm);
    const u32 sB = sA + 2 * GBUFB;
    const int tid = threadIdx.x, wid = tid >> 5, lane = tid & 31;
    const int wm = wid >> 1, wn = wid & 1;
    const int g = lane >> 2, t = lane & 3;
    const int row0 = blockIdx.y * 128, col0 = blockIdx.x * 128;

    float acc[4][8][4];
#pragma unroll
    for (int i = 0; i < 4; i++)
#pragma unroll
        for (int j = 0; j < 8; j++)
#pragma unroll
            for (int r = 0; r < 4; r++) acc[i][j][r] = 0.f;

    GEMM_MAINLOOP(acc)

#pragma unroll
    for (int mt = 0; mt < 4; mt++) {
        const int r0 = row0 + 64 * wm + 16 * mt + g;
#pragma unroll
        for (int nt = 0; nt < 8; nt++) {
            const int col = col0 + 64 * wn + 8 * nt + 2 * t;
            *(float2*)(C + (size_t)r0 * Nout + col)       = make_float2(acc[mt][nt][0], acc[mt][nt][1]);
            *(float2*)(C + (size_t)(r0 + 8) * Nout + col) = make_float2(acc[mt][nt][2], acc[mt][nt][3]);
        }
    }
}

// QKV GEMM: fused epilogue writes q/k/v bf16 hi/lo attention layouts directly.
__global__ void __launch_bounds__(128) gemm_qkv(
    const __nv_bfloat16* __restrict__ A, const __nv_bfloat16* __restrict__ Bt)
{
    extern __shared__ __align__(16) char sm[];
    const u32 sA = smem_u32(sm);
    const u32 sB = sA + 2 * GBUFB;
    const int tid = threadIdx.x, wid = tid >> 5, lane = tid & 31;
    const int wm = wid >> 1, wn = wid & 1;
    const int g = lane >> 2, t = lane & 3;
    const int row0 = blockIdx.y * 128, col0 = blockIdx.x * 128;

    float acc[4][8][4];
#pragma unroll
    for (int i = 0; i < 4; i++)
#pragma unroll
        for (int j = 0; j < 8; j++)
#pragma unroll
            for (int r = 0; r < 4; r++) acc[i][j][r] = 0.f;

    GEMM_MAINLOOP(acc)

    // epilogue: region = q/k/v, head h; write bf16 hi/lo split
    const int region = col0 >> 10;          // 0=Q, 1=K, 2=V
    __nv_bfloat16 *dh, *dl;
    float scale;
    if (region == 0)      { dh = g_qhi; dl = g_qlo; scale = 0.125f; }
    else if (region == 1) { dh = g_khi; dl = g_klo; scale = 1.f; }
    else                  { dh = g_vhi; dl = g_vlo; scale = 1.f; }
    const int h = ((col0 & 1023) >> 6) + wn;
    const int b = row0 >> 11;
    const size_t bhbase = ((size_t)(b * Hd + h)) * Td * 64;

#pragma unroll
    for (int mt = 0; mt < 4; mt++) {
        const int trow = (row0 & 2047) + 64 * wm + 16 * mt + g;
#pragma unroll
        for (int nt = 0; nt < 8; nt++) {
            const int d = 8 * nt + 2 * t;
            {
                const float f0 = acc[mt][nt][0] * scale, f1 = acc[mt][nt][1] * scale;
                const u32 hi = cvt_bf16x2(f1, f0);
                const u32 lo = cvt_bf16x2(f1 - bf_hi(hi), f0 - bf_lo(hi));
                const size_t off = bhbase + (size_t)trow * 64 + d;
                *(u32*)(dh + off) = hi;
                *(u32*)(dl + off) = lo;
            }
            {
                const float f2 = acc[mt][nt][2] * scale, f3 = acc[mt][nt][3] * scale;
                const u32 hi = cvt_bf16x2(f3, f2);
                const u32 lo = cvt_bf16x2(f3 - bf_hi(hi), f2 - bf_lo(hi));
                const size_t off = bhbase + (size_t)(trow + 8) * 64 + d;
                *(u32*)(dh + off) = hi;
                *(u32*)(dl + off) = lo;
            }
        }
    }
}

// ---------------------------------------------------------------------------
// flash_mma: q-tile 64, 4 warps x 16 q-rows (R5 structure). V row-major via
// ldmatrix.trans. Causal diag-tile MMA skip.
// ---------------------------------------------------------------------------
__global__ void __launch_bounds__(128) flash_mma(__nv_bfloat16* __restrict__ y3)
{
    __shared__ __align__(16) __nv_bfloat16 s_t[4][64 * 72];   // khi, klo, vhi, vlo
    const int tid = threadIdx.x, wid = tid >> 5, lane = tid & 31;
    const int g = lane >> 2, t = lane & 3;
    const int qb = gridDim.x - 1 - blockIdx.x;
    const int bh = blockIdx.y;
    const int b = bh >> 4, h = bh & 15;

    const size_t qkbase = (size_t)bh * Td * 64;

    const u32 s0 = smem_u32(s_t);
    const u32 sKhi = s0, sKlo = s0 + 9216, sVhi = s0 + 18432, sVlo = s0 + 27648;

    const int a_off = (16 * wid + (lane & 15)) * 144 + ((lane >> 4) << 4);
    const int b_off = ((lane & 7) + 8 * ((lane >> 4) & 1)) * 144 + 16 * ((lane >> 3) & 1);
    const int v_off = (lane & 15) * 144 + 16 * (lane >> 4);   // trans-ldmatrix base

#pragma unroll
    for (int i = 0; i < 4; i++) {
        const int u = tid + 128 * i;
        const int r = u >> 3, c = (u & 7) * 8;
        const size_t gq = qkbase + (size_t)(qb * 64 + r) * 64 + c;
        *(uint4*)&s_t[0][r * 72 + c] = *(const uint4*)(g_qhi + gq);
        *(uint4*)&s_t[1][r * 72 + c] = *(const uint4*)(g_qlo + gq);
    }
    __syncthreads();
    u32 qh[4][4], ql[4][4];
#pragma unroll
    for (int kt = 0; kt < 4; kt++) {
        ldm4(qh[kt][0], qh[kt][1], qh[kt][2], qh[kt][3], sKhi + a_off + kt * 32);
        ldm4(ql[kt][0], ql[kt][1], ql[kt][2], ql[kt][3], sKlo + a_off + kt * 32);
    }

    float o[8][4];
#pragma unroll
    for (int j = 0; j < 8; j++)
#pragma unroll
        for (int r = 0; r < 4; r++) o[j][r] = 0.f;
    float m0 = -1e30f, m1 = -1e30f, l0 = 0.f, l1 = 0.f;

    for (int kb = 0; kb <= qb; kb++) {
        const bool diag = (kb == qb);
        __syncthreads();
#pragma unroll
        for (int i = 0; i < 4; i++) {
            const int u = tid + 128 * i;
            const int r = u >> 3, c = (u & 7) * 8;
            const size_t gk = qkbase + (size_t)(kb * 64 + r) * 64 + c;
            *(uint4*)&s_t[0][r * 72 + c] = *(const uint4*)(g_khi + gk);
            *(uint4*)&s_t[1][r * 72 + c] = *(const uint4*)(g_klo + gk);
            *(uint4*)&s_t[2][r * 72 + c] = *(const uint4*)(g_vhi + gk);
            *(uint4*)&s_t[3][r * 72 + c] = *(const uint4*)(g_vlo + gk);
        }
        __syncthreads();

        float s[8][4];
#pragma unroll
        for (int j = 0; j < 8; j++)
#pragma unroll
            for (int r = 0; r < 4; r++) s[j][r] = 0.f;
#pragma unroll
        for (int np = 0; np < 4; np++) {
            if (diag && np > wid) continue;   // fully-masked column block
#pragma unroll
            for (int kt = 0; kt < 4; kt++) {
                const int off = b_off + np * (16 * 144) + kt * 32;
                u32 h0, h1, h2, h3, e0, e1, e2, e3;
                ldm4(h0, h1, h2, h3, sKhi + off);
                mma16816(s[2 * np],     qh[kt], h0, h1);
                mma16816(s[2 * np + 1], qh[kt], h2, h3);
                mma16816(s[2 * np],     ql[kt], h0, h1);
                mma16816(s[2 * np + 1], ql[kt], h2, h3);
                ldm4(e0, e1, e2, e3, sKlo + off);
                mma16816(s[2 * np],     qh[kt], e0, e1);
                mma16816(s[2 * np + 1], qh[kt], e2, e3);
            }
        }

        if (diag) {
            const int qg0 = qb * 64 + 16 * wid + g;
            const int qg1 = qg0 + 8;
#pragma unroll
            for (int nt = 0; nt < 8; nt++) {
                const int kg = kb * 64 + 8 * nt + 2 * t;
                if (kg > qg0)     s[nt][0] = -1e30f;
                if (kg + 1 > qg0) s[nt][1] = -1e30f;
                if (kg > qg1)     s[nt][2] = -1e30f;
                if (kg + 1 > qg1) s[nt][3] = -1e30f;
            }
        }

        float ml0 = -1e30f, ml1 = -1e30f;
#pragma unroll
        for (int nt = 0; nt < 8; nt++) {
            ml0 = fmaxf(ml0, fmaxf(s[nt][0], s[nt][1]));
            ml1 = fmaxf(ml1, fmaxf(s[nt][2], s[nt][3]));
        }
        ml0 = fmaxf(ml0, __shfl_xor_sync(0xffffffffu, ml0, 1));
        ml0 = fmaxf(ml0, __shfl_xor_sync(0xffffffffu, ml0, 2));
        ml1 = fmaxf(ml1, __shfl_xor_sync(0xffffffffu, ml1, 1));
        ml1 = fmaxf(ml1, __shfl_xor_sync(0xffffffffu, ml1, 2));
        const float mn0 = fmaxf(m0, ml0), mn1 = fmaxf(m1, ml1);
        const float cr0 = fexp(m0 - mn0), cr1 = fexp(m1 - mn1);
        m0 = mn0; m1 = mn1;
        float ls0 = 0.f, ls1 = 0.f;
#pragma unroll
        for (int nt = 0; nt < 8; nt++) {
            s[nt][0] = fexp(s[nt][0] - mn0); ls0 += s[nt][0];
            s[nt][1] = fexp(s[nt][1] - mn0); ls0 += s[nt][1];
            s[nt][2] = fexp(s[nt][2] - mn1); ls1 += s[nt][2];
            s[nt][3] = fexp(s[nt][3] - mn1); ls1 += s[nt][3];
        }
        ls0 += __shfl_xor_sync(0xffffffffu, ls0, 1);
        ls0 += __shfl_xor_sync(0xffffffffu, ls0, 2);
        ls1 += __shfl_xor_sync(0xffffffffu, ls1, 1);
        ls1 += __shfl_xor_sync(0xffffffffu, ls1, 2);
        l0 = l0 * cr0 + ls0;
        l1 = l1 * cr1 + ls1;
#pragma unroll
        for (int j = 0; j < 8; j++) {
            o[j][0] *= cr0; o[j][1] *= cr0; o[j][2] *= cr1; o[j][3] *= cr1;
        }

#pragma unroll
        for (int kt = 0; kt < 4; kt++) {
            if (diag && kt > wid) continue;   // P exactly 0 in this j block
            u32 ph[4], pl[4];
            ph[0] = cvt_bf16x2(s[2 * kt][1],     s[2 * kt][0]);
            ph[1] = cvt_bf16x2(s[2 * kt][3],     s[2 * kt][2]);
            ph[2] = cvt_bf16x2(s[2 * kt + 1][1], s[2 * kt + 1][0]);
            ph[3] = cvt_bf16x2(s[2 * kt + 1][3], s[2 * kt + 1][2]);
            pl[0] = cvt_bf16x2(s[2 * kt][1] - bf_hi(ph[0]),     s[2 * kt][0] - bf_lo(ph[0]));
            pl[1] = cvt_bf16x2(s[2 * kt][3] - bf_hi(ph[1]),     s[2 * kt][2] - bf_lo(ph[1]));
            pl[2] = cvt_bf16x2(s[2 * kt + 1][1] - bf_hi(ph[2]), s[2 * kt + 1][0] - bf_lo(ph[2]));
            pl[3] = cvt_bf16x2(s[2 * kt + 1][3] - bf_hi(ph[3]), s[2 * kt + 1][2] - bf_lo(ph[3]));
#pragma unroll
            for (int np = 0; np < 4; np++) {
                const int off = v_off + (16 * kt) * 144 + 32 * np;
                u32 v0, v1, v2, v3, w0, w1, w2, w3;
                ldm4t(v0, v1, v2, v3, sVhi + off);
                mma16816(o[2 * np],     ph, v0, v1);
                mma16816(o[2 * np + 1], ph, v2, v3);
                mma16816(o[2 * np],     pl, v0, v1);
                mma16816(o[2 * np + 1], pl, v2, v3);
                ldm4t(w0, w1, w2, w3, sVlo + off);
                mma16816(o[2 * np],     ph, w0, w1);
                mma16816(o[2 * np + 1], ph, w2, w3);
            }
        }
    }

    const float inv0 = 1.f / l0, inv1 = 1.f / l1;
    const int tg0 = qb * 64 + 16 * wid + g;
    const size_t m0i = (size_t)(b * Td + tg0) * K3;
    const size_t m1i = (size_t)(b * Td + tg0 + 8) * K3;
#pragma unroll
    for (int nt = 0; nt < 8; nt++) {
        const int col = h * 64 + 8 * nt + 2 * t;
        {
            const float f0 = o[nt][0] * inv0, f1 = o[nt][1] * inv0;
            const u32 hi = cvt_bf16x2(f1, f0);
            const u32 lo = cvt_bf16x2(f1 - bf_hi(hi), f0 - bf_lo(hi));
            *(u32*)(y3 + m0i + col)        = hi;
            *(u32*)(y3 + m0i + col + 1024) = hi;
            *(u32*)(y3 + m0i + col + 2048) = lo;
        }
        {
            const float f2 = o[nt][2] * inv1, f3 = o[nt][3] * inv1;
            const u32 hi = cvt_bf16x2(f3, f2);
            const u32 lo = cvt_bf16x2(f3 - bf_hi(hi), f2 - bf_lo(hi));
            *(u32*)(y3 + m1i + col)        = hi;
            *(u32*)(y3 + m1i + col + 1024) = hi;
            *(u32*)(y3 + m1i + col + 2048) = lo;
        }
    }
}

// ---------------------------------------------------------------------------
extern "C" void kernel_launch(void* const* d_in, const int* in_sizes, int n_in,
                              void* d_out, int out_size)
{
    const float* x      = (const float*)d_in[0];
    const float* w_attn = (const float*)d_in[1];
    const float* w_proj = (const float*)d_in[2];
    float* out = (float*)d_out;

    __nv_bfloat16 *x3, *y3, *wa3, *wp3;
    cudaGetSymbolAddress((void**)&x3, g_x3);
    cudaGetSymbolAddress((void**)&y3, g_y3);
    cudaGetSymbolAddress((void**)&wa3, g_wa3);
    cudaGetSymbolAddress((void**)&wp3, g_wp3);

    const int gemm_smem = 4 * GBUFB;        // 73728 B
    cudaFuncSetAttribute(gemm_mma, cudaFuncAttributeMaxDynamicSharedMemorySize, gemm_smem);
    cudaFuncSetAttribute(gemm_qkv, cudaFuncAttributeMaxDynamicSharedMemorySize, gemm_smem);

    split_rows3<<<(Mtot * Cd / 4 + 255) / 256, 256>>>(x, x3, Mtot, Cd);
    split_tr3<<<dim3(3 * Cd / 32, Cd / 32), 256>>>(w_attn, wa3, Cd, 3 * Cd);
    split_tr3<<<dim3(Cd / 32, Cd / 32), 256>>>(w_proj, wp3, Cd, Cd);

    // 1) QKV GEMM with fused split/reformat epilogue
    dim3 g1(3 * Cd / 128, Mtot / 128);    // (24, 64)
    gemm_qkv<<<g1, 128, gemm_smem>>>(x3, wa3);

    // 2) causal attention -> y3
    dim3 g2(Td / 64, Bd * Hd);            // (32, 64)
    flash_mma<<<g2, 128>>>(y3);

    // 3) proj GEMM
    dim3 g3(Cd / 128, Mtot / 128);        // (8, 64)
    gemm_mma<<<g3, 128, gemm_smem>>>(y3, wp3, out, Cd);
}

// round 10
// speedup vs baseline: 1.1072x; 1.0122x over previous
#include <cuda_runtime.h>
#include <cuda_bf16.h>
#include <math.h>
#include <stdint.h>

#define Bd 4
#define Td 2048
#define Cd 1024
#define Hd 16
#define DHd 64
#define Mtot (Bd * Td)      // 8192
#define K2 2048             // dedup split storage: [hi | lo]

typedef uint32_t u32;

// ---- scratch (__device__ globals; allocation-free rule) --------------------
__device__ __nv_bfloat16 g_x2[(size_t)Mtot * K2];          // [hi|lo]
__device__ __nv_bfloat16 g_y2[(size_t)Mtot * K2];          // [hi|lo]
__device__ __nv_bfloat16 g_wa2[(size_t)(3 * Cd) * K2];     // [hi|lo] (K-major, transposed)
__device__ __nv_bfloat16 g_wp2[(size_t)Cd * K2];           // [hi|lo]
// attention operands, per (b,h), all [bh][t][64] row-major
__device__ __nv_bfloat16 g_qhi[(size_t)Bd * Hd * Td * DHd];
__device__ __nv_bfloat16 g_qlo[(size_t)Bd * Hd * Td * DHd];
__device__ __nv_bfloat16 g_khi[(size_t)Bd * Hd * Td * DHd];
__device__ __nv_bfloat16 g_klo[(size_t)Bd * Hd * Td * DHd];
__device__ __nv_bfloat16 g_vhi[(size_t)Bd * Hd * Td * DHd];
__device__ __nv_bfloat16 g_vlo[(size_t)Bd * Hd * Td * DHd];

// ---- helpers ----------------------------------------------------------------
__device__ __forceinline__ u32 smem_u32(const void* p) {
    u32 a;
    asm("{ .reg .u64 t; cvta.to.shared.u64 t, %1; cvt.u32.u64 %0, t; }" : "=r"(a) : "l"(p));
    return a;
}
__device__ __forceinline__ void ldm4(u32& r0, u32& r1, u32& r2, u32& r3, u32 addr) {
    asm volatile("ldmatrix.sync.aligned.m8n8.x4.shared.b16 {%0,%1,%2,%3}, [%4];"
                 : "=r"(r0), "=r"(r1), "=r"(r2), "=r"(r3) : "r"(addr));
}
__device__ __forceinline__ void ldm4t(u32& r0, u32& r1, u32& r2, u32& r3, u32 addr) {
    asm volatile("ldmatrix.sync.aligned.m8n8.x4.trans.shared.b16 {%0,%1,%2,%3}, [%4];"
                 : "=r"(r0), "=r"(r1), "=r"(r2), "=r"(r3) : "r"(addr));
}
__device__ __forceinline__ void mma16816(float* d, const u32* a, u32 b0, u32 b1) {
    asm volatile(
        "mma.sync.aligned.m16n8k16.row.col.f32.bf16.bf16.f32 "
        "{%0,%1,%2,%3}, {%4,%5,%6,%7}, {%8,%9}, {%0,%1,%2,%3};"
        : "+f"(d[0]), "+f"(d[1]), "+f"(d[2]), "+f"(d[3])
        : "r"(a[0]), "r"(a[1]), "r"(a[2]), "r"(a[3]), "r"(b0), "r"(b1));
}
__device__ __forceinline__ void cpa16(u32 dst, const void* src) {
    asm volatile("cp.async.cg.shared.global [%0], [%1], 16;" :: "r"(dst), "l"(src) : "memory");
}
__device__ __forceinline__ void cpa_commit() {
    asm volatile("cp.async.commit_group;" ::: "memory");
}
__device__ __forceinline__ u32 cvt_bf16x2(float hi, float lo) {
    u32 r;
    asm("cvt.rn.bf16x2.f32 %0, %1, %2;" : "=r"(r) : "f"(hi), "f"(lo));
    return r;
}
__device__ __forceinline__ float bf_lo(u32 r) { return __uint_as_float(r << 16); }
__device__ __forceinline__ float bf_hi(u32 r) { return __uint_as_float(r & 0xFFFF0000u); }

// k-chunk source remap: logical K3 = A[hi|hi|lo] x B[hi|lo|hi], stored [hi|lo]
__device__ __forceinline__ int a_koff(int kc) { return (kc < 16 ? kc : kc - 16) * 64; }
__device__ __forceinline__ int b_koff(int kc) { return (kc < 32 ? kc : kc - 32) * 64; }

// FFMA-only exp (rel err ~1e-7), valid for x <= 0
__device__ __forceinline__ float fexp(float x) {
    x = fmaxf(x, -80.f);
    float t  = fmaf(x, 1.4426950408889634f, 12582912.0f);
    float fi = t - 12582912.0f;
    float f  = fmaf(x, 1.4426950408889634f, -fi);
    float p  = 0.00015403530393381609f;
    p = fmaf(p, f, 0.0013333558146428443f);
    p = fmaf(p, f, 0.009618129107628477f);
    p = fmaf(p, f, 0.05550410866482158f);
    p = fmaf(p, f, 0.2402265069591007f);
    p = fmaf(p, f, 0.6931471805599453f);
    p = fmaf(p, f, 1.0f);
    int ei = __float_as_int(t) - 0x4B400000;
    return __uint_as_float(__float_as_int(p) + (ei << 23));
}

// ---------------------------------------------------------------------------
// fp32 -> bf16 [hi|lo] split conversions
// ---------------------------------------------------------------------------
__global__ void split_rows2(const float* __restrict__ in, __nv_bfloat16* __restrict__ out,
                            int R, int Cc)
{
    int idx = blockIdx.x * blockDim.x + threadIdx.x;
    int total = R * Cc / 4;
    if (idx >= total) return;
    int c = (idx % (Cc / 4)) * 4;
    int r = idx / (Cc / 4);
    float4 v = *(const float4*)(in + (size_t)r * Cc + c);
    __nv_bfloat162 h0 = __floats2bfloat162_rn(v.x, v.y);
    __nv_bfloat162 h1 = __floats2bfloat162_rn(v.z, v.w);
    __nv_bfloat162 l0 = __floats2bfloat162_rn(v.x - __bfloat162float(h0.x),
                                              v.y - __bfloat162float(h0.y));
    __nv_bfloat162 l1 = __floats2bfloat162_rn(v.z - __bfloat162float(h1.x),
                                              v.w - __bfloat162float(h1.y));
    __nv_bfloat16* o = out + (size_t)r * (2 * Cc) + c;
    *(uint2*)(o)      = make_uint2(*(u32*)&h0, *(u32*)&h1);
    *(uint2*)(o + Cc) = make_uint2(*(u32*)&l0, *(u32*)&l1);
}

__global__ void __launch_bounds__(256) split_tr2(
    const float* __restrict__ w, __nv_bfloat16* __restrict__ out, int K, int N)
{
    __shared__ float tile[32][33];
    const int tid = threadIdx.x;
    const int n0 = blockIdx.x * 32, k0 = blockIdx.y * 32;
    {
        const int r = tid >> 3, c = (tid & 7) * 4;
        float4 v = *(const float4*)(w + (size_t)(k0 + r) * N + n0 + c);
        tile[r][c] = v.x; tile[r][c + 1] = v.y; tile[r][c + 2] = v.z; tile[r][c + 3] = v.w;
    }
    __syncthreads();
    {
        const int n = tid >> 3, c = (tid & 7) * 4;
        u32 hw[2], lw[2];
#pragma unroll
        for (int p = 0; p < 2; p++) {
            float v0 = tile[c + 2 * p][n], v1 = tile[c + 2 * p + 1][n];
            hw[p] = cvt_bf16x2(v1, v0);
            lw[p] = cvt_bf16x2(v1 - bf_hi(hw[p]), v0 - bf_lo(hw[p]));
        }
        __nv_bfloat16* o = out + (size_t)(n0 + n) * (2 * K) + k0 + c;
        *(uint2*)(o)     = make_uint2(hw[0], hw[1]);
        *(uint2*)(o + K) = make_uint2(lw[0], lw[1]);
    }
}

// ---------------------------------------------------------------------------
// GEMM mainloop (R5 structure) with dedup k-chunk remap. 48 logical chunks.
// ---------------------------------------------------------------------------
#define GROWB 144
#define GBUFB (128 * GROWB)       // A buffer (128 rows)
#define GBUFB64 (64 * GROWB)      // B buffer for n64 variant

#define GEMM_MAINLOOP(ACC, NROWS_B, GB_B)                                           \
    const int lr = tid >> 3;                                                        \
    const __nv_bfloat16* Ag = A + (size_t)(row0 + lr) * K2 + (tid & 7) * 8;         \
    const __nv_bfloat16* Bg = Bt + (size_t)(col0 + lr) * K2 + (tid & 7) * 8;        \
    const u32 da0 = sA + lr * GROWB + (tid & 7) * 16;                               \
    const u32 db0 = sB + lr * GROWB + (tid & 7) * 16;                               \
    _Pragma("unroll")                                                               \
    for (int i = 0; i < 8; i++)                                                     \
        cpa16(da0 + i * 16 * GROWB, Ag + (size_t)(16 * i) * K2);                    \
    _Pragma("unroll")                                                               \
    for (int i = 0; i < NROWS_B / 16; i++)                                          \
        cpa16(db0 + i * 16 * GROWB, Bg + (size_t)(16 * i) * K2);                    \
    cpa_commit();                                                                   \
    for (int kc = 0; kc < 48; kc++) {                                               \
        const int buf = kc & 1;                                                     \
        if (kc < 47) {                                                              \
            const int nb = buf ^ 1;                                                 \
            const size_t koA = (size_t)a_koff(kc + 1);                              \
            const size_t koB = (size_t)b_koff(kc + 1);                              \
            _Pragma("unroll")                                                       \
            for (int i = 0; i < 8; i++)                                             \
                cpa16(da0 + nb * GBUFB + i * 16 * GROWB, Ag + (size_t)(16 * i) * K2 + koA); \
            _Pragma("unroll")                                                       \
            for (int i = 0; i < NROWS_B / 16; i++)                                  \
                cpa16(db0 + nb * GB_B + i * 16 * GROWB, Bg + (size_t)(16 * i) * K2 + koB); \
            cpa_commit();                                                           \
            asm volatile("cp.async.wait_group 1;" ::: "memory");                    \
        } else {                                                                    \
            asm volatile("cp.async.wait_group 0;" ::: "memory");                    \
        }                                                                           \
        __syncthreads();                                                            \
        const u32 abase = sA + buf * GBUFB + a_row_off;                             \
        const u32 bbase = sB + buf * GB_B + b_row_off;                              \
        _Pragma("unroll")                                                           \
        for (int kt = 0; kt < 4; kt++) {                                            \
            u32 af[4][4], bf[NROWS_B / 16][4];                                      \
            _Pragma("unroll")                                                       \
            for (int mt = 0; mt < 4; mt++)                                          \
                ldm4(af[mt][0], af[mt][1], af[mt][2], af[mt][3],                    \
                     abase + mt * (16 * GROWB) + kt * 32);                          \
            _Pragma("unroll")                                                       \
            for (int np = 0; np < NROWS_B / 32; np++)                               \
                ldm4(bf[np][0], bf[np][1], bf[np][2], bf[np][3],                    \
                     bbase + np * (16 * GROWB) + kt * 32);                          \
            _Pragma("unroll")                                                       \
            for (int mt = 0; mt < 4; mt++)                                          \
                _Pragma("unroll")                                                   \
                for (int np = 0; np < NROWS_B / 32; np++) {                         \
                    mma16816(ACC[mt][2 * np],     af[mt], bf[np][0], bf[np][1]);    \
                    mma16816(ACC[mt][2 * np + 1], af[mt], bf[np][2], bf[np][3]);    \
                }                                                                   \
        }                                                                           \
        __syncthreads();                                                            \
    }

// QKV GEMM: 128x128, fused epilogue writes q/k/v bf16 hi/lo layouts.
__global__ void __launch_bounds__(128) gemm_qkv(
    const __nv_bfloat16* __restrict__ A, const __nv_bfloat16* __restrict__ Bt)
{
    extern __shared__ __align__(16) char sm[];
    const u32 sA = smem_u32(sm);
    const u32 sB = sA + 2 * GBUFB;
    const int tid = threadIdx.x, wid = tid >> 5, lane = tid & 31;
    const int wm = wid >> 1, wn = wid & 1;
    const int g = lane >> 2, t = lane & 3;
    const int row0 = blockIdx.y * 128, col0 = blockIdx.x * 128;

    const int a_row_off = (64 * wm + (lane & 15)) * GROWB + ((lane >> 4) << 4);
    const int b_row_off = (64 * wn + (lane & 7) + 8 * ((lane >> 4) & 1)) * GROWB
                        + 16 * ((lane >> 3) & 1);

    float acc[4][8][4];
#pragma unroll
    for (int i = 0; i < 4; i++)
#pragma unroll
        for (int j = 0; j < 8; j++)
#pragma unroll
            for (int r = 0; r < 4; r++) acc[i][j][r] = 0.f;

    GEMM_MAINLOOP(acc, 128, GBUFB)

    const int region = col0 >> 10;          // 0=Q, 1=K, 2=V
    __nv_bfloat16 *dh, *dl;
    float scale;
    if (region == 0)      { dh = g_qhi; dl = g_qlo; scale = 0.125f; }
    else if (region == 1) { dh = g_khi; dl = g_klo; scale = 1.f; }
    else                  { dh = g_vhi; dl = g_vlo; scale = 1.f; }
    const int h = ((col0 & 1023) >> 6) + wn;
    const int b = row0 >> 11;
    const size_t bhbase = ((size_t)(b * Hd + h)) * Td * 64;

#pragma unroll
    for (int mt = 0; mt < 4; mt++) {
        const int trow = (row0 & 2047) + 64 * wm + 16 * mt + g;
#pragma unroll
        for (int nt = 0; nt < 8; nt++) {
            const int d = 8 * nt + 2 * t;
            {
                const float f0 = acc[mt][nt][0] * scale, f1 = acc[mt][nt][1] * scale;
                const u32 hi = cvt_bf16x2(f1, f0);
                const u32 lo = cvt_bf16x2(f1 - bf_hi(hi), f0 - bf_lo(hi));
                const size_t off = bhbase + (size_t)trow * 64 + d;
                *(u32*)(dh + off) = hi;
                *(u32*)(dl + off) = lo;
            }
            {
                const float f2 = acc[mt][nt][2] * scale, f3 = acc[mt][nt][3] * scale;
                const u32 hi = cvt_bf16x2(f3, f2);
                const u32 lo = cvt_bf16x2(f3 - bf_hi(hi), f2 - bf_lo(hi));
                const size_t off = bhbase + (size_t)(trow + 8) * 64 + d;
                *(u32*)(dh + off) = hi;
                *(u32*)(dl + off) = lo;
            }
        }
    }
}

// Proj GEMM: 128x64 tile (tail-quantization fix), fp32 output.
__global__ void __launch_bounds__(128) gemm_proj(
    const __nv_bfloat16* __restrict__ A, const __nv_bfloat16* __restrict__ Bt,
    float* __restrict__ C, int Nout)
{
    extern __shared__ __align__(16) char sm[];
    const u32 sA = smem_u32(sm);
    const u32 sB = sA + 2 * GBUFB;
    const int tid = threadIdx.x, wid = tid >> 5, lane = tid & 31;
    const int wm = wid >> 1, wn = wid & 1;
    const int g = lane >> 2, t = lane & 3;
    const int row0 = blockIdx.y * 128, col0 = blockIdx.x * 64;

    const int a_row_off = (64 * wm + (lane & 15)) * GROWB + ((lane >> 4) << 4);
    const int b_row_off = (32 * wn + (lane & 7) + 8 * ((lane >> 4) & 1)) * GROWB
                        + 16 * ((lane >> 3) & 1);

    float acc[4][4][4];
#pragma unroll
    for (int i = 0; i < 4; i++)
#pragma unroll
        for (int j = 0; j < 4; j++)
#pragma unroll
            for (int r = 0; r < 4; r++) acc[i][j][r] = 0.f;

    GEMM_MAINLOOP(acc, 64, GBUFB64)

#pragma unroll
    for (int mt = 0; mt < 4; mt++) {
        const int r0 = row0 + 64 * wm + 16 * mt + g;
#pragma unroll
        for (int nt = 0; nt < 4; nt++) {
            const int col = col0 + 32 * wn + 8 * nt + 2 * t;
            *(float2*)(C + (size_t)r0 * Nout + col)       = make_float2(acc[mt][nt][0], acc[mt][nt][1]);
            *(float2*)(C + (size_t)(r0 + 8) * Nout + col) = make_float2(acc[mt][nt][2], acc[mt][nt][3]);
        }
    }
}

// ---------------------------------------------------------------------------
// flash_mma: q-tile 64, 4 warps x 16 q-rows. V row-major via ldmatrix.trans.
// Causal diag-tile MMA skip. Epilogue writes y2 [hi|lo].
// ---------------------------------------------------------------------------
__global__ void __launch_bounds__(128) flash_mma(__nv_bfloat16* __restrict__ y2)
{
    __shared__ __align__(16) __nv_bfloat16 s_t[4][64 * 72];   // khi, klo, vhi, vlo
    const int tid = threadIdx.x, wid = tid >> 5, lane = tid & 31;
    const int g = lane >> 2, t = lane & 3;
    const int qb = gridDim.x - 1 - blockIdx.x;
    const int bh = blockIdx.y;
    const int b = bh >> 4, h = bh & 15;

    const size_t qkbase = (size_t)bh * Td * 64;

    const u32 s0 = smem_u32(s_t);
    const u32 sKhi = s0, sKlo = s0 + 9216, sVhi = s0 + 18432, sVlo = s0 + 27648;

    const int a_off = (16 * wid + (lane & 15)) * 144 + ((lane >> 4) << 4);
    const int b_off = ((lane & 7) + 8 * ((lane >> 4) & 1)) * 144 + 16 * ((lane >> 3) & 1);
    const int v_off = (lane & 15) * 144 + 16 * (lane >> 4);

#pragma unroll
    for (int i = 0; i < 4; i++) {
        const int u = tid + 128 * i;
        const int r = u >> 3, c = (u & 7) * 8;
        const size_t gq = qkbase + (size_t)(qb * 64 + r) * 64 + c;
        *(uint4*)&s_t[0][r * 72 + c] = *(const uint4*)(g_qhi + gq);
        *(uint4*)&s_t[1][r * 72 + c] = *(const uint4*)(g_qlo + gq);
    }
    __syncthreads();
    u32 qh[4][4], ql[4][4];
#pragma unroll
    for (int kt = 0; kt < 4; kt++) {
        ldm4(qh[kt][0], qh[kt][1], qh[kt][2], qh[kt][3], sKhi + a_off + kt * 32);
        ldm4(ql[kt][0], ql[kt][1], ql[kt][2], ql[kt][3], sKlo + a_off + kt * 32);
    }

    float o[8][4];
#pragma unroll
    for (int j = 0; j < 8; j++)
#pragma unroll
        for (int r = 0; r < 4; r++) o[j][r] = 0.f;
    float m0 = -1e30f, m1 = -1e30f, l0 = 0.f, l1 = 0.f;

    for (int kb = 0; kb <= qb; kb++) {
        const bool diag = (kb == qb);
        __syncthreads();
#pragma unroll
        for (int i = 0; i < 4; i++) {
            const int u = tid + 128 * i;
            const int r = u >> 3, c = (u & 7) * 8;
            const size_t gk = qkbase + (size_t)(kb * 64 + r) * 64 + c;
            *(uint4*)&s_t[0][r * 72 + c] = *(const uint4*)(g_khi + gk);
            *(uint4*)&s_t[1][r * 72 + c] = *(const uint4*)(g_klo + gk);
            *(uint4*)&s_t[2][r * 72 + c] = *(const uint4*)(g_vhi + gk);
            *(uint4*)&s_t[3][r * 72 + c] = *(const uint4*)(g_vlo + gk);
        }
        __syncthreads();

        float s[8][4];
#pragma unroll
        for (int j = 0; j < 8; j++)
#pragma unroll
            for (int r = 0; r < 4; r++) s[j][r] = 0.f;
#pragma unroll
        for (int np = 0; np < 4; np++) {
            if (diag && np > wid) continue;
#pragma unroll
            for (int kt = 0; kt < 4; kt++) {
                const int off = b_off + np * (16 * 144) + kt * 32;
                u32 h0, h1, h2, h3, e0, e1, e2, e3;
                ldm4(h0, h1, h2, h3, sKhi + off);
                mma16816(s[2 * np],     qh[kt], h0, h1);
                mma16816(s[2 * np + 1], qh[kt], h2, h3);
                mma16816(s[2 * np],     ql[kt], h0, h1);
                mma16816(s[2 * np + 1], ql[kt], h2, h3);
                ldm4(e0, e1, e2, e3, sKlo + off);
                mma16816(s[2 * np],     qh[kt], e0, e1);
                mma16816(s[2 * np + 1], qh[kt], e2, e3);
            }
        }

        if (diag) {
            const int qg0 = qb * 64 + 16 * wid + g;
            const int qg1 = qg0 + 8;
#pragma unroll
            for (int nt = 0; nt < 8; nt++) {
                const int kg = kb * 64 + 8 * nt + 2 * t;
                if (kg > qg0)     s[nt][0] = -1e30f;
                if (kg + 1 > qg0) s[nt][1] = -1e30f;
                if (kg > qg1)     s[nt][2] = -1e30f;
                if (kg + 1 > qg1) s[nt][3] = -1e30f;
            }
        }

        float ml0 = -1e30f, ml1 = -1e30f;
#pragma unroll
        for (int nt = 0; nt < 8; nt++) {
            ml0 = fmaxf(ml0, fmaxf(s[nt][0], s[nt][1]));
            ml1 = fmaxf(ml1, fmaxf(s[nt][2], s[nt][3]));
        }
        ml0 = fmaxf(ml0, __shfl_xor_sync(0xffffffffu, ml0, 1));
        ml0 = fmaxf(ml0, __shfl_xor_sync(0xffffffffu, ml0, 2));
        ml1 = fmaxf(ml1, __shfl_xor_sync(0xffffffffu, ml1, 1));
        ml1 = fmaxf(ml1, __shfl_xor_sync(0xffffffffu, ml1, 2));
        const float mn0 = fmaxf(m0, ml0), mn1 = fmaxf(m1, ml1);
        const float cr0 = fexp(m0 - mn0), cr1 = fexp(m1 - mn1);
        m0 = mn0; m1 = mn1;
        float ls0 = 0.f, ls1 = 0.f;
#pragma unroll
        for (int nt = 0; nt < 8; nt++) {
            s[nt][0] = fexp(s[nt][0] - mn0); ls0 += s[nt][0];
            s[nt][1] = fexp(s[nt][1] - mn0); ls0 += s[nt][1];
            s[nt][2] = fexp(s[nt][2] - mn1); ls1 += s[nt][2];
            s[nt][3] = fexp(s[nt][3] - mn1); ls1 += s[nt][3];
        }
        ls0 += __shfl_xor_sync(0xffffffffu, ls0, 1);
        ls0 += __shfl_xor_sync(0xffffffffu, ls0, 2);
        ls1 += __shfl_xor_sync(0xffffffffu, ls1, 1);
        ls1 += __shfl_xor_sync(0xffffffffu, ls1, 2);
        l0 = l0 * cr0 + ls0;
        l1 = l1 * cr1 + ls1;
#pragma unroll
        for (int j = 0; j < 8; j++) {
            o[j][0] *= cr0; o[j][1] *= cr0; o[j][2] *= cr1; o[j][3] *= cr1;
        }

#pragma unroll
        for (int kt = 0; kt < 4; kt++) {
            if (diag && kt > wid) continue;
            u32 ph[4], pl[4];
            ph[0] = cvt_bf16x2(s[2 * kt][1],     s[2 * kt][0]);
            ph[1] = cvt_bf16x2(s[2 * kt][3],     s[2 * kt][2]);
            ph[2] = cvt_bf16x2(s[2 * kt + 1][1], s[2 * kt + 1][0]);
            ph[3] = cvt_bf16x2(s[2 * kt + 1][3], s[2 * kt + 1][2]);
            pl[0] = cvt_bf16x2(s[2 * kt][1] - bf_hi(ph[0]),     s[2 * kt][0] - bf_lo(ph[0]));
            pl[1] = cvt_bf16x2(s[2 * kt][3] - bf_hi(ph[1]),     s[2 * kt][2] - bf_lo(ph[1]));
            pl[2] = cvt_bf16x2(s[2 * kt + 1][1] - bf_hi(ph[2]), s[2 * kt + 1][0] - bf_lo(ph[2]));
            pl[3] = cvt_bf16x2(s[2 * kt + 1][3] - bf_hi(ph[3]), s[2 * kt + 1][2] - bf_lo(ph[3]));
#pragma unroll
            for (int np = 0; np < 4; np++) {
                const int off = v_off + (16 * kt) * 144 + 32 * np;
                u32 v0, v1, v2, v3, w0, w1, w2, w3;
                ldm4t(v0, v1, v2, v3, sVhi + off);
                mma16816(o[2 * np],     ph, v0, v1);
                mma16816(o[2 * np + 1], ph, v2, v3);
                mma16816(o[2 * np],     pl, v0, v1);
                mma16816(o[2 * np + 1], pl, v2, v3);
                ldm4t(w0, w1, w2, w3, sVlo + off);
                mma16816(o[2 * np],     ph, w0, w1);
                mma16816(o[2 * np + 1], ph, w2, w3);
            }
        }
    }

    const float inv0 = 1.f / l0, inv1 = 1.f / l1;
    const int tg0 = qb * 64 + 16 * wid + g;
    const size_t m0i = (size_t)(b * Td + tg0) * K2;
    const size_t m1i = (size_t)(b * Td + tg0 + 8) * K2;
#pragma unroll
    for (int nt = 0; nt < 8; nt++) {
        const int col = h * 64 + 8 * nt + 2 * t;
        {
            const float f0 = o[nt][0] * inv0, f1 = o[nt][1] * inv0;
            const u32 hi = cvt_bf16x2(f1, f0);
            const u32 lo = cvt_bf16x2(f1 - bf_hi(hi), f0 - bf_lo(hi));
            *(u32*)(y2 + m0i + col)        = hi;
            *(u32*)(y2 + m0i + col + 1024) = lo;
        }
        {
            const float f2 = o[nt][2] * inv1, f3 = o[nt][3] * inv1;
            const u32 hi = cvt_bf16x2(f3, f2);
            const u32 lo = cvt_bf16x2(f3 - bf_hi(hi), f2 - bf_lo(hi));
            *(u32*)(y2 + m1i + col)        = hi;
            *(u32*)(y2 + m1i + col + 1024) = lo;
        }
    }
}

// ---------------------------------------------------------------------------
extern "C" void kernel_launch(void* const* d_in, const int* in_sizes, int n_in,
                              void* d_out, int out_size)
{
    const float* x      = (const float*)d_in[0];
    const float* w_attn = (const float*)d_in[1];
    const float* w_proj = (const float*)d_in[2];
    float* out = (float*)d_out;

    __nv_bfloat16 *x2, *y2, *wa2, *wp2;
    cudaGetSymbolAddress((void**)&x2, g_x2);
    cudaGetSymbolAddress((void**)&y2, g_y2);
    cudaGetSymbolAddress((void**)&wa2, g_wa2);
    cudaGetSymbolAddress((void**)&wp2, g_wp2);

    const int qkv_smem  = 4 * GBUFB;                 // 73728 B
    const int proj_smem = 2 * GBUFB + 2 * GBUFB64;   // 55296 B
    cudaFuncSetAttribute(gemm_qkv,  cudaFuncAttributeMaxDynamicSharedMemorySize, qkv_smem);
    cudaFuncSetAttribute(gemm_proj, cudaFuncAttributeMaxDynamicSharedMemorySize, proj_smem);

    split_rows2<<<(Mtot * Cd / 4 + 255) / 256, 256>>>(x, x2, Mtot, Cd);
    split_tr2<<<dim3(3 * Cd / 32, Cd / 32), 256>>>(w_attn, wa2, Cd, 3 * Cd);
    split_tr2<<<dim3(Cd / 32, Cd / 32), 256>>>(w_proj, wp2, Cd, Cd);

    // 1) QKV GEMM with fused split/reformat epilogue
    dim3 g1(3 * Cd / 128, Mtot / 128);    // (24, 64)
    gemm_qkv<<<g1, 128, qkv_smem>>>(x2, wa2);

    // 2) causal attention -> y2
    dim3 g2(Td / 64, Bd * Hd);            // (32, 64)
    flash_mma<<<g2, 128>>>(y2);

    // 3) proj GEMM (128x64 tiles)
    dim3 g3(Cd / 64, Mtot / 128);         // (16, 64)
    gemm_proj<<<g3, 128, proj_smem>>>(y2, wp2, out, Cd);
}

// round 11
// speedup vs baseline: 1.1204x; 1.0120x over previous
#include <cuda_runtime.h>
#include <cuda_bf16.h>
#include <math.h>
#include <stdint.h>

#define Bd 4
#define Td 2048
#define Cd 1024
#define Hd 16
#define DHd 64
#define Mtot (Bd * Td)      // 8192
#define K2 2048             // dedup split storage: [hi | lo]

typedef uint32_t u32;

// ---- scratch (__device__ globals; allocation-free rule) --------------------
__device__ __nv_bfloat16 g_x2[(size_t)Mtot * K2];          // [hi|lo]
__device__ __nv_bfloat16 g_y2[(size_t)Mtot * K2];          // [hi|lo]
__device__ __nv_bfloat16 g_wa2[(size_t)(3 * Cd) * K2];     // [hi|lo] (K-major, transposed)
__device__ __nv_bfloat16 g_wp2[(size_t)Cd * K2];           // [hi|lo]
// attention operands, per (b,h), all [bh][t][64] row-major
__device__ __nv_bfloat16 g_qhi[(size_t)Bd * Hd * Td * DHd];
__device__ __nv_bfloat16 g_qlo[(size_t)Bd * Hd * Td * DHd];
__device__ __nv_bfloat16 g_khi[(size_t)Bd * Hd * Td * DHd];
__device__ __nv_bfloat16 g_klo[(size_t)Bd * Hd * Td * DHd];
__device__ __nv_bfloat16 g_vhi[(size_t)Bd * Hd * Td * DHd];
__device__ __nv_bfloat16 g_vlo[(size_t)Bd * Hd * Td * DHd];

// ---- helpers ----------------------------------------------------------------
__device__ __forceinline__ u32 smem_u32(const void* p) {
    u32 a;
    asm("{ .reg .u64 t; cvta.to.shared.u64 t, %1; cvt.u32.u64 %0, t; }" : "=r"(a) : "l"(p));
    return a;
}
__device__ __forceinline__ void ldm4(u32& r0, u32& r1, u32& r2, u32& r3, u32 addr) {
    asm volatile("ldmatrix.sync.aligned.m8n8.x4.shared.b16 {%0,%1,%2,%3}, [%4];"
                 : "=r"(r0), "=r"(r1), "=r"(r2), "=r"(r3) : "r"(addr));
}
__device__ __forceinline__ void ldm4t(u32& r0, u32& r1, u32& r2, u32& r3, u32 addr) {
    asm volatile("ldmatrix.sync.aligned.m8n8.x4.trans.shared.b16 {%0,%1,%2,%3}, [%4];"
                 : "=r"(r0), "=r"(r1), "=r"(r2), "=r"(r3) : "r"(addr));
}
__device__ __forceinline__ void mma16816(float* d, const u32* a, u32 b0, u32 b1) {
    asm volatile(
        "mma.sync.aligned.m16n8k16.row.col.f32.bf16.bf16.f32 "
        "{%0,%1,%2,%3}, {%4,%5,%6,%7}, {%8,%9}, {%0,%1,%2,%3};"
        : "+f"(d[0]), "+f"(d[1]), "+f"(d[2]), "+f"(d[3])
        : "r"(a[0]), "r"(a[1]), "r"(a[2]), "r"(a[3]), "r"(b0), "r"(b1));
}
__device__ __forceinline__ void cpa16(u32 dst, const void* src) {
    asm volatile("cp.async.cg.shared.global [%0], [%1], 16;" :: "r"(dst), "l"(src) : "memory");
}
__device__ __forceinline__ void cpa_commit() {
    asm volatile("cp.async.commit_group;" ::: "memory");
}
__device__ __forceinline__ u32 cvt_bf16x2(float hi, float lo) {
    u32 r;
    asm("cvt.rn.bf16x2.f32 %0, %1, %2;" : "=r"(r) : "f"(hi), "f"(lo));
    return r;
}
__device__ __forceinline__ float bf_lo(u32 r) { return __uint_as_float(r << 16); }
__device__ __forceinline__ float bf_hi(u32 r) { return __uint_as_float(r & 0xFFFF0000u); }

// k-chunk source remap: logical K3 = A[hi|hi|lo] x B[hi|lo|hi], stored [hi|lo]
__device__ __forceinline__ int a_koff(int kc) { return (kc < 16 ? kc : kc - 16) * 64; }
__device__ __forceinline__ int b_koff(int kc) { return (kc < 32 ? kc : kc - 32) * 64; }

// FFMA-only exp (rel err ~1e-7), valid for x <= 0
__device__ __forceinline__ float fexp(float x) {
    x = fmaxf(x, -80.f);
    float t  = fmaf(x, 1.4426950408889634f, 12582912.0f);
    float fi = t - 12582912.0f;
    float f  = fmaf(x, 1.4426950408889634f, -fi);
    float p  = 0.00015403530393381609f;
    p = fmaf(p, f, 0.0013333558146428443f);
    p = fmaf(p, f, 0.009618129107628477f);
    p = fmaf(p, f, 0.05550410866482158f);
    p = fmaf(p, f, 0.2402265069591007f);
    p = fmaf(p, f, 0.6931471805599453f);
    p = fmaf(p, f, 1.0f);
    int ei = __float_as_int(t) - 0x4B400000;
    return __uint_as_float(__float_as_int(p) + (ei << 23));
}

// ---------------------------------------------------------------------------
// fp32 -> bf16 [hi|lo] split conversions
// ---------------------------------------------------------------------------
__global__ void split_rows2(const float* __restrict__ in, __nv_bfloat16* __restrict__ out,
                            int R, int Cc)
{
    int idx = blockIdx.x * blockDim.x + threadIdx.x;
    int total = R * Cc / 4;
    if (idx >= total) return;
    int c = (idx % (Cc / 4)) * 4;
    int r = idx / (Cc / 4);
    float4 v = *(const float4*)(in + (size_t)r * Cc + c);
    __nv_bfloat162 h0 = __floats2bfloat162_rn(v.x, v.y);
    __nv_bfloat162 h1 = __floats2bfloat162_rn(v.z, v.w);
    __nv_bfloat162 l0 = __floats2bfloat162_rn(v.x - __bfloat162float(h0.x),
                                              v.y - __bfloat162float(h0.y));
    __nv_bfloat162 l1 = __floats2bfloat162_rn(v.z - __bfloat162float(h1.x),
                                              v.w - __bfloat162float(h1.y));
    __nv_bfloat16* o = out + (size_t)r * (2 * Cc) + c;
    *(uint2*)(o)      = make_uint2(*(u32*)&h0, *(u32*)&h1);
    *(uint2*)(o + Cc) = make_uint2(*(u32*)&l0, *(u32*)&l1);
}

__global__ void __launch_bounds__(256) split_tr2(
    const float* __restrict__ w, __nv_bfloat16* __restrict__ out, int K, int N)
{
    __shared__ float tile[32][33];
    const int tid = threadIdx.x;
    const int n0 = blockIdx.x * 32, k0 = blockIdx.y * 32;
    {
        const int r = tid >> 3, c = (tid & 7) * 4;
        float4 v = *(const float4*)(w + (size_t)(k0 + r) * N + n0 + c);
        tile[r][c] = v.x; tile[r][c + 1] = v.y; tile[r][c + 2] = v.z; tile[r][c + 3] = v.w;
    }
    __syncthreads();
    {
        const int n = tid >> 3, c = (tid & 7) * 4;
        u32 hw[2], lw[2];
#pragma unroll
        for (int p = 0; p < 2; p++) {
            float v0 = tile[c + 2 * p][n], v1 = tile[c + 2 * p + 1][n];
            hw[p] = cvt_bf16x2(v1, v0);
            lw[p] = cvt_bf16x2(v1 - bf_hi(hw[p]), v0 - bf_lo(hw[p]));
        }
        __nv_bfloat16* o = out + (size_t)(n0 + n) * (2 * K) + k0 + c;
        *(uint2*)(o)     = make_uint2(hw[0], hw[1]);
        *(uint2*)(o + K) = make_uint2(lw[0], lw[1]);
    }
}

// ---------------------------------------------------------------------------
// GEMM mainloop (R5 structure) with dedup k-chunk remap. 48 logical chunks.
// ---------------------------------------------------------------------------
#define GROWB 144
#define GBUFB (128 * GROWB)       // A buffer (128 rows)
#define GBUFB64 (64 * GROWB)      // B buffer for n64 variant

#define GEMM_MAINLOOP(ACC, NROWS_B, GB_B)                                           \
    const int lr = tid >> 3;                                                        \
    const __nv_bfloat16* Ag = A + (size_t)(row0 + lr) * K2 + (tid & 7) * 8;         \
    const __nv_bfloat16* Bg = Bt + (size_t)(col0 + lr) * K2 + (tid & 7) * 8;        \
    const u32 da0 = sA + lr * GROWB + (tid & 7) * 16;                               \
    const u32 db0 = sB + lr * GROWB + (tid & 7) * 16;                               \
    _Pragma("unroll")                                                               \
    for (int i = 0; i < 8; i++)                                                     \
        cpa16(da0 + i * 16 * GROWB, Ag + (size_t)(16 * i) * K2);                    \
    _Pragma("unroll")                                                               \
    for (int i = 0; i < NROWS_B / 16; i++)                                          \
        cpa16(db0 + i * 16 * GROWB, Bg + (size_t)(16 * i) * K2);                    \
    cpa_commit();                                                                   \
    for (int kc = 0; kc < 48; kc++) {                                               \
        const int buf = kc & 1;                                                     \
        if (kc < 47) {                                                              \
            const int nb = buf ^ 1;                                                 \
            const size_t koA = (size_t)a_koff(kc + 1);                              \
            const size_t koB = (size_t)b_koff(kc + 1);                              \
            _Pragma("unroll")                                                       \
            for (int i = 0; i < 8; i++)                                             \
                cpa16(da0 + nb * GBUFB + i * 16 * GROWB, Ag + (size_t)(16 * i) * K2 + koA); \
            _Pragma("unroll")                                                       \
            for (int i = 0; i < NROWS_B / 16; i++)                                  \
                cpa16(db0 + nb * GB_B + i * 16 * GROWB, Bg + (size_t)(16 * i) * K2 + koB); \
            cpa_commit();                                                           \
            asm volatile("cp.async.wait_group 1;" ::: "memory");                    \
        } else {                                                                    \
            asm volatile("cp.async.wait_group 0;" ::: "memory");                    \
        }                                                                           \
        __syncthreads();                                                            \
        const u32 abase = sA + buf * GBUFB + a_row_off;                             \
        const u32 bbase = sB + buf * GB_B + b_row_off;                              \
        _Pragma("unroll")                                                           \
        for (int kt = 0; kt < 4; kt++) {                                            \
            u32 af[4][4], bf[NROWS_B / 16][4];                                      \
            _Pragma("unroll")                                                       \
            for (int mt = 0; mt < 4; mt++)                                          \
                ldm4(af[mt][0], af[mt][1], af[mt][2], af[mt][3],                    \
                     abase + mt * (16 * GROWB) + kt * 32);                          \
            _Pragma("unroll")                                                       \
            for (int np = 0; np < NROWS_B / 32; np++)                               \
                ldm4(bf[np][0], bf[np][1], bf[np][2], bf[np][3],                    \
                     bbase + np * (16 * GROWB) + kt * 32);                          \
            _Pragma("unroll")                                                       \
            for (int mt = 0; mt < 4; mt++)                                          \
                _Pragma("unroll")                                                   \
                for (int np = 0; np < NROWS_B / 32; np++) {                         \
                    mma16816(ACC[mt][2 * np],     af[mt], bf[np][0], bf[np][1]);    \
                    mma16816(ACC[mt][2 * np + 1], af[mt], bf[np][2], bf[np][3]);    \
                }                                                                   \
        }                                                                           \
        __syncthreads();                                                            \
    }

// QKV GEMM: 128x128, fused epilogue -> smem staging -> coalesced stores.
__global__ void __launch_bounds__(128) gemm_qkv(
    const __nv_bfloat16* __restrict__ A, const __nv_bfloat16* __restrict__ Bt)
{
    extern __shared__ __align__(16) char sm[];
    const u32 sA = smem_u32(sm);
    const u32 sB = sA + 2 * GBUFB;
    const int tid = threadIdx.x, wid = tid >> 5, lane = tid & 31;
    const int wm = wid >> 1, wn = wid & 1;
    const int g = lane >> 2, t = lane & 3;
    const int row0 = blockIdx.y * 128, col0 = blockIdx.x * 128;

    const int a_row_off = (64 * wm + (lane & 15)) * GROWB + ((lane >> 4) << 4);
    const int b_row_off = (64 * wn + (lane & 7) + 8 * ((lane >> 4) & 1)) * GROWB
                        + 16 * ((lane >> 3) & 1);

    float acc[4][8][4];
#pragma unroll
    for (int i = 0; i < 4; i++)
#pragma unroll
        for (int j = 0; j < 8; j++)
#pragma unroll
            for (int r = 0; r < 4; r++) acc[i][j][r] = 0.f;

    GEMM_MAINLOOP(acc, 128, GBUFB)

    const int region = col0 >> 10;          // 0=Q, 1=K, 2=V
    __nv_bfloat16 *dh, *dl;
    float scale;
    if (region == 0)      { dh = g_qhi; dl = g_qlo; scale = 0.125f; }
    else if (region == 1) { dh = g_khi; dl = g_klo; scale = 1.f; }
    else                  { dh = g_vhi; dl = g_vlo; scale = 1.f; }

    // stage tile: hi/lo u32 arrays, rows padded to 68 words (272B)
    u32* st_hi = (u32*)sm;                    // 128*68*4 = 34816 B
    u32* st_lo = (u32*)(sm + 34816);          // total 69632 <= 73728
#pragma unroll
    for (int mt = 0; mt < 4; mt++) {
        const int r0 = 64 * wm + 16 * mt + g;
#pragma unroll
        for (int nt = 0; nt < 8; nt++) {
            const int cw = 32 * wn + 4 * nt + t;   // u32 col word 0..63
            {
                const float f0 = acc[mt][nt][0] * scale, f1 = acc[mt][nt][1] * scale;
                const u32 hi = cvt_bf16x2(f1, f0);
                const u32 lo = cvt_bf16x2(f1 - bf_hi(hi), f0 - bf_lo(hi));
                st_hi[r0 * 68 + cw] = hi;
                st_lo[r0 * 68 + cw] = lo;
            }
            {
                const float f2 = acc[mt][nt][2] * scale, f3 = acc[mt][nt][3] * scale;
                const u32 hi = cvt_bf16x2(f3, f2);
                const u32 lo = cvt_bf16x2(f3 - bf_hi(hi), f2 - bf_lo(hi));
                st_hi[(r0 + 8) * 68 + cw] = hi;
                st_lo[(r0 + 8) * 68 + cw] = lo;
            }
        }
    }
    __syncthreads();

    // coalesced copy-out: 2 arrays x 128 rows x 16 uint4
    const int h0 = (col0 & 1023) >> 6;
    const int b = row0 >> 11;
    const int trow0 = row0 & 2047;
#pragma unroll
    for (int i = 0; i < 16; i++) {           // hi
        const int idx = tid + 128 * i;       // 0..2047
        const int r = idx >> 4, seg = idx & 15;
        const int head = h0 + (seg >> 3);
        uint4 v = *(const uint4*)(st_hi + r * 68 + seg * 4);
        *(uint4*)(dh + ((size_t)(b * Hd + head)) * Td * 64
                     + (size_t)(trow0 + r) * 64 + (seg & 7) * 8) = v;
    }
#pragma unroll
    for (int i = 0; i < 16; i++) {           // lo
        const int idx = tid + 128 * i;
        const int r = idx >> 4, seg = idx & 15;
        const int head = h0 + (seg >> 3);
        uint4 v = *(const uint4*)(st_lo + r * 68 + seg * 4);
        *(uint4*)(dl + ((size_t)(b * Hd + head)) * Td * 64
                     + (size_t)(trow0 + r) * 64 + (seg & 7) * 8) = v;
    }
}

// Proj GEMM: 128x64 tile, fp32 output via smem staging.
__global__ void __launch_bounds__(128) gemm_proj(
    const __nv_bfloat16* __restrict__ A, const __nv_bfloat16* __restrict__ Bt,
    float* __restrict__ C, int Nout)
{
    extern __shared__ __align__(16) char sm[];
    const u32 sA = smem_u32(sm);
    const u32 sB = sA + 2 * GBUFB;
    const int tid = threadIdx.x, wid = tid >> 5, lane = tid & 31;
    const int wm = wid >> 1, wn = wid & 1;
    const int g = lane >> 2, t = lane & 3;
    const int row0 = blockIdx.y * 128, col0 = blockIdx.x * 64;

    const int a_row_off = (64 * wm + (lane & 15)) * GROWB + ((lane >> 4) << 4);
    const int b_row_off = (32 * wn + (lane & 7) + 8 * ((lane >> 4) & 1)) * GROWB
                        + 16 * ((lane >> 3) & 1);

    float acc[4][4][4];
#pragma unroll
    for (int i = 0; i < 4; i++)
#pragma unroll
        for (int j = 0; j < 4; j++)
#pragma unroll
            for (int r = 0; r < 4; r++) acc[i][j][r] = 0.f;

    GEMM_MAINLOOP(acc, 64, GBUFB64)

    // stage: 128 rows x 64 fp32, rows padded to 68 words (272B) = 34816 B
    float* st = (float*)sm;
#pragma unroll
    for (int mt = 0; mt < 4; mt++) {
        const int r0 = 64 * wm + 16 * mt + g;
#pragma unroll
        for (int nt = 0; nt < 4; nt++) {
            const int col = 32 * wn + 8 * nt + 2 * t;
            *(float2*)(st + r0 * 68 + col)       = make_float2(acc[mt][nt][0], acc[mt][nt][1]);
            *(float2*)(st + (r0 + 8) * 68 + col) = make_float2(acc[mt][nt][2], acc[mt][nt][3]);
        }
    }
    __syncthreads();
#pragma unroll
    for (int i = 0; i < 16; i++) {
        const int idx = tid + 128 * i;       // 0..2047
        const int r = idx >> 4, seg = idx & 15;
        float4 v = *(const float4*)(st + r * 68 + seg * 4);
        *(float4*)(C + (size_t)(row0 + r) * Nout + col0 + seg * 4) = v;
    }
}

// ---------------------------------------------------------------------------
// flash_mma: q-tile 64, 4 warps x 16 q-rows. V row-major via ldmatrix.trans.
// Causal diag-tile MMA skip. Epilogue staged in smem -> coalesced y2 stores.
// ---------------------------------------------------------------------------
__global__ void __launch_bounds__(128) flash_mma(__nv_bfloat16* __restrict__ y2)
{
    __shared__ __align__(16) __nv_bfloat16 s_t[4][64 * 72];   // khi, klo, vhi, vlo
    const int tid = threadIdx.x, wid = tid >> 5, lane = tid & 31;
    const int g = lane >> 2, t = lane & 3;
    const int qb = gridDim.x - 1 - blockIdx.x;
    const int bh = blockIdx.y;
    const int b = bh >> 4, h = bh & 15;

    const size_t qkbase = (size_t)bh * Td * 64;

    const u32 s0 = smem_u32(s_t);
    const u32 sKhi = s0, sKlo = s0 + 9216, sVhi = s0 + 18432, sVlo = s0 + 27648;

    const int a_off = (16 * wid + (lane & 15)) * 144 + ((lane >> 4) << 4);
    const int b_off = ((lane & 7) + 8 * ((lane >> 4) & 1)) * 144 + 16 * ((lane >> 3) & 1);
    const int v_off = (lane & 15) * 144 + 16 * (lane >> 4);

#pragma unroll
    for (int i = 0; i < 4; i++) {
        const int u = tid + 128 * i;
        const int r = u >> 3, c = (u & 7) * 8;
        const size_t gq = qkbase + (size_t)(qb * 64 + r) * 64 + c;
        *(uint4*)&s_t[0][r * 72 + c] = *(const uint4*)(g_qhi + gq);
        *(uint4*)&s_t[1][r * 72 + c] = *(const uint4*)(g_qlo + gq);
    }
    __syncthreads();
    u32 qh[4][4], ql[4][4];
#pragma unroll
    for (int kt = 0; kt < 4; kt++) {
        ldm4(qh[kt][0], qh[kt][1], qh[kt][2], qh[kt][3], sKhi + a_off + kt * 32);
        ldm4(ql[kt][0], ql[kt][1], ql[kt][2], ql[kt][3], sKlo + a_off + kt * 32);
    }

    float o[8][4];
#pragma unroll
    for (int j = 0; j < 8; j++)
#pragma unroll
        for (int r = 0; r < 4; r++) o[j][r] = 0.f;
    float m0 = -1e30f, m1 = -1e30f, l0 = 0.f, l1 = 0.f;

    for (int kb = 0; kb <= qb; kb++) {
        const bool diag = (kb == qb);
        __syncthreads();
#pragma unroll
        for (int i = 0; i < 4; i++) {
            const int u = tid + 128 * i;
            const int r = u >> 3, c = (u & 7) * 8;
            const size_t gk = qkbase + (size_t)(kb * 64 + r) * 64 + c;
            *(uint4*)&s_t[0][r * 72 + c] = *(const uint4*)(g_khi + gk);
            *(uint4*)&s_t[1][r * 72 + c] = *(const uint4*)(g_klo + gk);
            *(uint4*)&s_t[2][r * 72 + c] = *(const uint4*)(g_vhi + gk);
            *(uint4*)&s_t[3][r * 72 + c] = *(const uint4*)(g_vlo + gk);
        }
        __syncthreads();

        float s[8][4];
#pragma unroll
        for (int j = 0; j < 8; j++)
#pragma unroll
            for (int r = 0; r < 4; r++) s[j][r] = 0.f;
#pragma unroll
        for (int np = 0; np < 4; np++) {
            if (diag && np > wid) continue;
#pragma unroll
            for (int kt = 0; kt < 4; kt++) {
                const int off = b_off + np * (16 * 144) + kt * 32;
                u32 h0, h1, h2, h3, e0, e1, e2, e3;
                ldm4(h0, h1, h2, h3, sKhi + off);
                mma16816(s[2 * np],     qh[kt], h0, h1);
                mma16816(s[2 * np + 1], qh[kt], h2, h3);
                mma16816(s[2 * np],     ql[kt], h0, h1);
                mma16816(s[2 * np + 1], ql[kt], h2, h3);
                ldm4(e0, e1, e2, e3, sKlo + off);
                mma16816(s[2 * np],     qh[kt], e0, e1);
                mma16816(s[2 * np + 1], qh[kt], e2, e3);
            }
        }

        if (diag) {
            const int qg0 = qb * 64 + 16 * wid + g;
            const int qg1 = qg0 + 8;
#pragma unroll
            for (int nt = 0; nt < 8; nt++) {
                const int kg = kb * 64 + 8 * nt + 2 * t;
                if (kg > qg0)     s[nt][0] = -1e30f;
                if (kg + 1 > qg0) s[nt][1] = -1e30f;
                if (kg > qg1)     s[nt][2] = -1e30f;
                if (kg + 1 > qg1) s[nt][3] = -1e30f;
            }
        }

        float ml0 = -1e30f, ml1 = -1e30f;
#pragma unroll
        for (int nt = 0; nt < 8; nt++) {
            ml0 = fmaxf(ml0, fmaxf(s[nt][0], s[nt][1]));
            ml1 = fmaxf(ml1, fmaxf(s[nt][2], s[nt][3]));
        }
        ml0 = fmaxf(ml0, __shfl_xor_sync(0xffffffffu, ml0, 1));
        ml0 = fmaxf(ml0, __shfl_xor_sync(0xffffffffu, ml0, 2));
        ml1 = fmaxf(ml1, __shfl_xor_sync(0xffffffffu, ml1, 1));
        ml1 = fmaxf(ml1, __shfl_xor_sync(0xffffffffu, ml1, 2));
        const float mn0 = fmaxf(m0, ml0), mn1 = fmaxf(m1, ml1);
        const float cr0 = fexp(m0 - mn0), cr1 = fexp(m1 - mn1);
        m0 = mn0; m1 = mn1;
        float ls0 = 0.f, ls1 = 0.f;
#pragma unroll
        for (int nt = 0; nt < 8; nt++) {
            s[nt][0] = fexp(s[nt][0] - mn0); ls0 += s[nt][0];
            s[nt][1] = fexp(s[nt][1] - mn0); ls0 += s[nt][1];
            s[nt][2] = fexp(s[nt][2] - mn1); ls1 += s[nt][2];
            s[nt][3] = fexp(s[nt][3] - mn1); ls1 += s[nt][3];
        }
        ls0 += __shfl_xor_sync(0xffffffffu, ls0, 1);
        ls0 += __shfl_xor_sync(0xffffffffu, ls0, 2);
        ls1 += __shfl_xor_sync(0xffffffffu, ls1, 1);
        ls1 += __shfl_xor_sync(0xffffffffu, ls1, 2);
        l0 = l0 * cr0 + ls0;
        l1 = l1 * cr1 + ls1;
#pragma unroll
        for (int j = 0; j < 8; j++) {
            o[j][0] *= cr0; o[j][1] *= cr0; o[j][2] *= cr1; o[j][3] *= cr1;
        }

#pragma unroll
        for (int kt = 0; kt < 4; kt++) {
            if (diag && kt > wid) continue;
            u32 ph[4], pl[4];
            ph[0] = cvt_bf16x2(s[2 * kt][1],     s[2 * kt][0]);
            ph[1] = cvt_bf16x2(s[2 * kt][3],     s[2 * kt][2]);
            ph[2] = cvt_bf16x2(s[2 * kt + 1][1], s[2 * kt + 1][0]);
            ph[3] = cvt_bf16x2(s[2 * kt + 1][3], s[2 * kt + 1][2]);
            pl[0] = cvt_bf16x2(s[2 * kt][1] - bf_hi(ph[0]),     s[2 * kt][0] - bf_lo(ph[0]));
            pl[1] = cvt_bf16x2(s[2 * kt][3] - bf_hi(ph[1]),     s[2 * kt][2] - bf_lo(ph[1]));
            pl[2] = cvt_bf16x2(s[2 * kt + 1][1] - bf_hi(ph[2]), s[2 * kt + 1][0] - bf_lo(ph[2]));
            pl[3] = cvt_bf16x2(s[2 * kt + 1][3] - bf_hi(ph[3]), s[2 * kt + 1][2] - bf_lo(ph[3]));
#pragma unroll
            for (int np = 0; np < 4; np++) {
                const int off = v_off + (16 * kt) * 144 + 32 * np;
                u32 v0, v1, v2, v3, w0, w1, w2, w3;
                ldm4t(v0, v1, v2, v3, sVhi + off);
                mma16816(o[2 * np],     ph, v0, v1);
                mma16816(o[2 * np + 1], ph, v2, v3);
                mma16816(o[2 * np],     pl, v0, v1);
                mma16816(o[2 * np + 1], pl, v2, v3);
                ldm4t(w0, w1, w2, w3, sVlo + off);
                mma16816(o[2 * np],     ph, w0, w1);
                mma16816(o[2 * np + 1], ph, w2, w3);
            }
        }
    }

    // ---- epilogue: stage O hi/lo in smem (rows 36 words), coalesced stores ----
    __syncthreads();
    u32* st_hi = (u32*)&s_t[0][0];           // 64*36*4 = 9216 B
    u32* st_lo = st_hi + 64 * 36;            // next 9216 B
    const float inv0 = 1.f / l0, inv1 = 1.f / l1;
#pragma unroll
    for (int nt = 0; nt < 8; nt++) {
        const int cw = 4 * nt + t;           // u32 col word 0..31
        const int r0 = 16 * wid + g;
        {
            const float f0 = o[nt][0] * inv0, f1 = o[nt][1] * inv0;
            const u32 hi = cvt_bf16x2(f1, f0);
            const u32 lo = cvt_bf16x2(f1 - bf_hi(hi), f0 - bf_lo(hi));
            st_hi[r0 * 36 + cw] = hi;
            st_lo[r0 * 36 + cw] = lo;
        }
        {
            const float f2 = o[nt][2] * inv1, f3 = o[nt][3] * inv1;
            const u32 hi = cvt_bf16x2(f3, f2);
            const u32 lo = cvt_bf16x2(f3 - bf_hi(hi), f2 - bf_lo(hi));
            st_hi[(r0 + 8) * 36 + cw] = hi;
            st_lo[(r0 + 8) * 36 + cw] = lo;
        }
    }
    __syncthreads();
#pragma unroll
    for (int i = 0; i < 8; i++) {
        const int idx = tid + 128 * i;       // 0..1023
        const int arr = idx >> 9;            // 0=hi, 1=lo
        const int j = idx & 511;
        const int r = j >> 3, seg = j & 7;
        uint4 v = *(const uint4*)((arr ? st_lo : st_hi) + r * 36 + seg * 4);
        *(uint4*)(y2 + (size_t)(b * Td + qb * 64 + r) * K2
                     + h * 64 + seg * 8 + arr * 1024) = v;
    }
}

// ---------------------------------------------------------------------------
extern "C" void kernel_launch(void* const* d_in, const int* in_sizes, int n_in,
                              void* d_out, int out_size)
{
    const float* x      = (const float*)d_in[0];
    const float* w_attn = (const float*)d_in[1];
    const float* w_proj = (const float*)d_in[2];
    float* out = (float*)d_out;

    __nv_bfloat16 *x2, *y2, *wa2, *wp2;
    cudaGetSymbolAddress((void**)&x2, g_x2);
    cudaGetSymbolAddress((void**)&y2, g_y2);
    cudaGetSymbolAddress((void**)&wa2, g_wa2);
    cudaGetSymbolAddress((void**)&wp2, g_wp2);

    const int qkv_smem  = 4 * GBUFB;                 // 73728 B
    const int proj_smem = 2 * GBUFB + 2 * GBUFB64;   // 55296 B
    cudaFuncSetAttribute(gemm_qkv,  cudaFuncAttributeMaxDynamicSharedMemorySize, qkv_smem);
    cudaFuncSetAttribute(gemm_proj, cudaFuncAttributeMaxDynamicSharedMemorySize, proj_smem);

    split_rows2<<<(Mtot * Cd / 4 + 255) / 256, 256>>>(x, x2, Mtot, Cd);
    split_tr2<<<dim3(3 * Cd / 32, Cd / 32), 256>>>(w_attn, wa2, Cd, 3 * Cd);
    split_tr2<<<dim3(Cd / 32, Cd / 32), 256>>>(w_proj, wp2, Cd, Cd);

    // 1) QKV GEMM with fused split/reformat epilogue
    dim3 g1(3 * Cd / 128, Mtot / 128);    // (24, 64)
    gemm_qkv<<<g1, 128, qkv_smem>>>(x2, wa2);

    // 2) causal attention -> y2
    dim3 g2(Td / 64, Bd * Hd);            // (32, 64)
    flash_mma<<<g2, 128>>>(y2);

    // 3) proj GEMM (128x64 tiles)
    dim3 g3(Cd / 64, Mtot / 128);         // (16, 64)
    gemm_proj<<<g3, 128, proj_smem>>>(y2, wp2, out, Cd);
}